// round 5
// baseline (speedup 1.0000x reference)
#include <cuda_runtime.h>
#include <math.h>
#include <stdint.h>

#define NN 40000
#define EE 320000

// ---------------- device scratch ----------------
__device__ float g_P[(size_t)NN * 768];
__device__ float g_sxe[(size_t)NN * 512];
__device__ float g_pre[NN * 128];
__device__ float g_att[NN * 128];
__device__ float g_inter[(size_t)NN * 512];
__device__ float g_m[NN * 128];
__device__ float g_h[NN * 128];
__device__ float g_x[NN * 128];
__device__ float g_gi[(size_t)NN * 384];
__device__ float g_gh[(size_t)NN * 384];
__device__ float g_WprojF[768 * 128];
__device__ float g_Wav4F[128 * 512];
__device__ float g_bproj[768];
__device__ float g_bav[128];
// tf32 hi/lo weight chunk-images: each = [hi 128x36 | lo 128x36] = 9216 fp32 words
__device__ float g_img[(size_t)96 * 9216];
__device__ int g_cnt[NN], g_rowptr[NN + 1], g_cur[NN], g_srcs[EE], g_eidxs[EE];

#define IMG_PROJ 0
#define IMG_WAV4 24
#define IMG_WINT 40
#define IMG_WOUT 56
#define IMG_WIH  72
#define IMG_WHH  84

// ---------------- helpers ----------------
__device__ __forceinline__ uint32_t f2tf(float x) {
    uint32_t r;
    asm("cvt.rna.tf32.f32 %0, %1;" : "=r"(r) : "f"(x));
    return r;
}
__device__ __forceinline__ void mma_tf32(float* d, const uint32_t* a, const uint32_t* b) {
    asm volatile(
        "mma.sync.aligned.m16n8k8.row.col.f32.tf32.tf32.f32 "
        "{%0,%1,%2,%3}, {%4,%5,%6,%7}, {%8,%9}, {%0,%1,%2,%3};"
        : "+f"(d[0]), "+f"(d[1]), "+f"(d[2]), "+f"(d[3])
        : "r"(a[0]), "r"(a[1]), "r"(a[2]), "r"(a[3]), "r"(b[0]), "r"(b[1]));
}

// ---------------- fused prep #1: fold weights + biases + zero cnt ----------------
__global__ void build_all(const float* __restrict__ wq, const float* __restrict__ wk,
                          const float* __restrict__ wv, const float* __restrict__ wao,
                          const float* __restrict__ bq, const float* __restrict__ bk,
                          const float* __restrict__ bv, const float* __restrict__ bao) {
    int idx = blockIdx.x * blockDim.x + threadIdx.x;
    const float SC = 0.17677669529663687f;
    if (idx < 98304) {                       // WprojF [768 x 128]
        int n = idx >> 7, k = idx & 127;
        float v;
        if (n < 128) v = wq[n * 128 + k] * SC;
        else if (n < 256) v = wk[(n - 128) * 128 + k];
        else {
            int h = (n - 256) >> 7, d1 = (n - 256) & 127;
            float s = 0.f;
            for (int r = 0; r < 32; r++)
                s += wk[(h * 32 + r) * 128 + d1] * wq[(h * 32 + r) * 128 + k];
            v = s * SC;
        }
        g_WprojF[idx] = v;
    } else if (idx < 163840) {               // Wav4F [128 x 512]
        int i2 = idx - 98304;
        int n = i2 >> 9, m = i2 & 511;
        int h = m >> 7, d = m & 127;
        float s = 0.f;
        for (int r = 0; r < 32; r++)
            s += wao[n * 128 + h * 32 + r] * wv[(h * 32 + r) * 128 + d];
        g_Wav4F[i2] = s;
    } else if (idx < 164608) {               // bproj [768]
        int n = idx - 163840;
        float v;
        if (n < 128) v = bq[n] * SC;
        else if (n < 256) v = bk[n - 128];
        else {
            int h = (n - 256) >> 7, d1 = (n - 256) & 127;
            float s = 0.f;
            for (int r = 0; r < 32; r++)
                s += wk[(h * 32 + r) * 128 + d1] * bq[h * 32 + r];
            v = s * SC;
        }
        g_bproj[n] = v;
    } else if (idx < 164736) {               // bav [128]
        int n = idx - 164608;
        float s = 0.f;
        for (int k = 0; k < 128; k++) s += wao[n * 128 + k] * bv[k];
        g_bav[n] = s + bao[n];
    } else if (idx < 204736) {               // zero cnt
        g_cnt[idx - 164736] = 0;
    }
}

// ---------------- fused prep #2: all weights -> tf32 hi/lo chunk-images ----------------
__device__ __forceinline__ void img_write(const float* src, int i2, int K, int base) {
    int n = i2 / K, k = i2 % K;
    float v = src[i2];
    float hi = __uint_as_float(f2tf(v));
    float lo = __uint_as_float(f2tf(v - hi));
    int KC = K >> 5;
    size_t w = ((size_t)(base + (n >> 7) * KC + (k >> 5))) * 9216 + (n & 127) * 36 + (k & 31);
    g_img[w] = hi;
    g_img[w + 4608] = lo;
}
__global__ void prep_w_all(const float* __restrict__ wint, const float* __restrict__ wout,
                           const float* __restrict__ wih, const float* __restrict__ whh) {
    int idx = blockIdx.x * blockDim.x + threadIdx.x;
    if (idx < 98304)       img_write(g_WprojF, idx, 128, IMG_PROJ);
    else if (idx < 163840) img_write(g_Wav4F, idx - 98304, 512, IMG_WAV4);
    else if (idx < 229376) img_write(wint, idx - 163840, 128, IMG_WINT);
    else if (idx < 294912) img_write(wout, idx - 229376, 512, IMG_WOUT);
    else if (idx < 344064) img_write(wih, idx - 294912, 128, IMG_WIH);
    else if (idx < 393216) img_write(whh, idx - 344064, 128, IMG_WHH);
}

// ---------------- CSR build ----------------
__global__ void hist_kernel(const int* __restrict__ dst) {
    int i = blockIdx.x * blockDim.x + threadIdx.x;
    if (i < EE) atomicAdd(&g_cnt[dst[i]], 1);
}
__global__ void scan_kernel() {
    __shared__ int part[1024];
    int t = threadIdx.x;
    const int per = (NN + 1023) / 1024;
    int base = t * per, s = 0;
    for (int i = 0; i < per; i++) { int idx = base + i; if (idx < NN) s += g_cnt[idx]; }
    part[t] = s;
    __syncthreads();
    if (t == 0) {
        int r = 0;
        for (int i = 0; i < 1024; i++) { int v = part[i]; part[i] = r; r += v; }
        g_rowptr[NN] = r;
    }
    __syncthreads();
    int r = part[t];
    for (int i = 0; i < per; i++) {
        int idx = base + i;
        if (idx < NN) { g_rowptr[idx] = r; g_cur[idx] = r; r += g_cnt[idx]; }
    }
}
__global__ void scatter_kernel(const int* __restrict__ src, const int* __restrict__ dst) {
    int i = blockIdx.x * blockDim.x + threadIdx.x;
    if (i >= EE) return;
    int d = dst[i];
    int p = atomicAdd(&g_cur[d], 1);
    g_srcs[p] = src[i];
    g_eidxs[p] = i;
}

// ---------------- tf32 3-term pipelined GEMM ----------------
// C[M, ytiles*128] = A[M,lda] @ W^T. K-chunk=32, smem: Ah|Al (128x36 each) + B [hi|lo].
// 8 warps: 4m x 2n; warp tile 32x64 = 2x8 m16n8k8 tiles; 3 split terms.
// EPI: 1 bias, 2 bias+residual, 3 bias+gelu
template <int EPI>
__global__ void __launch_bounds__(256) gemm_tf(
    const float* __restrict__ A, int lda,
    const float* __restrict__ img,
    const float* __restrict__ bias, const float* __restrict__ res,
    float* __restrict__ out, int M, int KC, int ldo)
{
    extern __shared__ float sm[];
    float* AhS = sm;            // 4608
    float* AlS = sm + 4608;     // 4608
    float* BS  = sm + 9216;     // 9216 = [hi 4608 | lo 4608]

    const int tid = threadIdx.x;
    const int warp = tid >> 5, lane = tid & 31;
    const int wm = warp >> 1, wn = warp & 1;
    const int lr = lane >> 2, lk = lane & 3;
    const int bm = blockIdx.x * 128;

    float acc[2][8][4];
#pragma unroll
    for (int i = 0; i < 2; i++)
#pragma unroll
        for (int j = 0; j < 8; j++)
#pragma unroll
            for (int l = 0; l < 4; l++) acc[i][j][l] = 0.f;

    int gr = bm + (tid >> 1);
    if (gr >= M) gr = M - 1;
    const float* asrc = A + (size_t)gr * lda + (tid & 1) * 16;
    const int abase = (tid >> 1) * 36 + (tid & 1) * 16;
    const float* bsrc = img + (size_t)blockIdx.y * KC * 9216;

    float4 av[4], bv[9];
#pragma unroll
    for (int j = 0; j < 4; j++) av[j] = *(const float4*)(asrc + j * 4);
#pragma unroll
    for (int j = 0; j < 9; j++) bv[j] = *(const float4*)(bsrc + (j * 256 + tid) * 4);

    for (int c = 0; c < KC; c++) {
        // write staged chunk to smem (A with tf32 hi/lo split)
#pragma unroll
        for (int j = 0; j < 4; j++) {
            const float* f = (const float*)&av[j];
#pragma unroll
            for (int q = 0; q < 4; q++) {
                float hi = __uint_as_float(f2tf(f[q]));
                AhS[abase + j * 4 + q] = hi;
                AlS[abase + j * 4 + q] = __uint_as_float(f2tf(f[q] - hi));
            }
        }
#pragma unroll
        for (int j = 0; j < 9; j++) *(float4*)(BS + (j * 256 + tid) * 4) = bv[j];
        __syncthreads();

        // prefetch next chunk while computing this one
        if (c + 1 < KC) {
            const float* a2 = asrc + (c + 1) * 32;
#pragma unroll
            for (int j = 0; j < 4; j++) av[j] = *(const float4*)(a2 + j * 4);
            const float* b2 = bsrc + (size_t)(c + 1) * 9216;
#pragma unroll
            for (int j = 0; j < 9; j++) bv[j] = *(const float4*)(b2 + (j * 256 + tid) * 4);
        }

#pragma unroll
        for (int s = 0; s < 4; s++) {
            const int akp = s * 8 + lk;
            uint32_t ah[2][4], al[2][4];
#pragma unroll
            for (int mt = 0; mt < 2; mt++) {
                int rb = (wm * 32 + mt * 16 + lr) * 36 + akp;
                ah[mt][0] = __float_as_uint(AhS[rb]);
                ah[mt][1] = __float_as_uint(AhS[rb + 288]);
                ah[mt][2] = __float_as_uint(AhS[rb + 4]);
                ah[mt][3] = __float_as_uint(AhS[rb + 292]);
                al[mt][0] = __float_as_uint(AlS[rb]);
                al[mt][1] = __float_as_uint(AlS[rb + 288]);
                al[mt][2] = __float_as_uint(AlS[rb + 4]);
                al[mt][3] = __float_as_uint(AlS[rb + 292]);
            }
#pragma unroll
            for (int nt = 0; nt < 8; nt++) {
                int nb = (wn * 64 + nt * 8 + lr) * 36 + akp;
                uint32_t bh[2], bl[2];
                bh[0] = __float_as_uint(BS[nb]);
                bh[1] = __float_as_uint(BS[nb + 4]);
                bl[0] = __float_as_uint(BS[4608 + nb]);
                bl[1] = __float_as_uint(BS[4608 + nb + 4]);
#pragma unroll
                for (int mt = 0; mt < 2; mt++) {
                    mma_tf32(acc[mt][nt], ah[mt], bh);
                    mma_tf32(acc[mt][nt], ah[mt], bl);
                    mma_tf32(acc[mt][nt], al[mt], bh);
                }
            }
        }
        __syncthreads();
    }

    // epilogue
    const int cbase = blockIdx.y * 128 + wn * 64;
#pragma unroll
    for (int mt = 0; mt < 2; mt++) {
        int r0 = bm + wm * 32 + mt * 16 + lr;
#pragma unroll
        for (int half = 0; half < 2; half++) {
            int row = r0 + half * 8;
            if (row >= M) continue;
            float* orow = out + (size_t)row * ldo + cbase;
            const float* rrow = (EPI == 2) ? (res + (size_t)row * ldo + cbase) : nullptr;
#pragma unroll
            for (int nt = 0; nt < 8; nt++) {
                int cl = nt * 8 + lk * 2;
                float v0 = acc[mt][nt][half * 2 + 0];
                float v1 = acc[mt][nt][half * 2 + 1];
                v0 += bias[cbase + cl];
                v1 += bias[cbase + cl + 1];
                if (EPI == 2) { v0 += rrow[cl]; v1 += rrow[cl + 1]; }
                if (EPI == 3) {
                    v0 = 0.5f * v0 * (1.f + erff(v0 * 0.70710678118654752f));
                    v1 = 0.5f * v1 * (1.f + erff(v1 * 0.70710678118654752f));
                }
                *(float2*)(orow + cl) = make_float2(v0, v1);
            }
        }
    }
}

// ---------------- GAT: warp per node, per-head online softmax ----------------
__global__ void gat2_kernel(const float* __restrict__ eattr, const float* __restrict__ xsrc) {
    int w = (blockIdx.x * blockDim.x + threadIdx.x) >> 5;
    int lane = threadIdx.x & 31;
    if (w >= NN) return;
    float q[4], qe[4][4], mx[4], smx[4], acc[4][4];
    const float* Pw = g_P + (size_t)w * 768;
#pragma unroll
    for (int j = 0; j < 4; j++) q[j] = Pw[j * 32 + lane];
#pragma unroll
    for (int h = 0; h < 4; h++) {
#pragma unroll
        for (int j = 0; j < 4; j++) {
            qe[h][j] = Pw[256 + h * 128 + j * 32 + lane];
            acc[h][j] = 0.f;
        }
        mx[h] = -1e30f; smx[h] = 0.f;
    }
    int beg = g_rowptr[w], end = g_rowptr[w + 1];
    for (int p = beg; p < end; p++) {
        int s = g_srcs[p], ei = g_eidxs[p];
        const float* kp = g_P + (size_t)s * 768 + 128;
        const float* xp = xsrc + (size_t)s * 128;
        const float* ep = eattr + (size_t)ei * 128;
        float ks[4], ev[4], u[4];
#pragma unroll
        for (int j = 0; j < 4; j++) {
            ks[j] = kp[j * 32 + lane];
            ev[j] = ep[j * 32 + lane];
            u[j] = xp[j * 32 + lane] + ev[j];
        }
        float d[4];
#pragma unroll
        for (int h = 0; h < 4; h++)
            d[h] = q[h] * ks[h] + qe[h][0] * ev[0] + qe[h][1] * ev[1]
                 + qe[h][2] * ev[2] + qe[h][3] * ev[3];
#pragma unroll
        for (int off = 16; off > 0; off >>= 1)
#pragma unroll
            for (int h = 0; h < 4; h++)
                d[h] += __shfl_xor_sync(0xffffffffu, d[h], off);
#pragma unroll
        for (int h = 0; h < 4; h++) {
            float a = d[h];
            float nm = fmaxf(mx[h], a);
            float csc = __expf(mx[h] - nm);
            float pe = __expf(a - nm);
            smx[h] = smx[h] * csc + pe;
#pragma unroll
            for (int j = 0; j < 4; j++)
                acc[h][j] = acc[h][j] * csc + pe * u[j];
            mx[h] = nm;
        }
    }
    float* o = g_sxe + (size_t)w * 512;
#pragma unroll
    for (int h = 0; h < 4; h++) {
        float inv = 1.f / (smx[h] + 1e-16f);
#pragma unroll
        for (int j = 0; j < 4; j++)
            o[h * 128 + j * 32 + lane] = acc[h][j] * inv;
    }
}

// ---------------- LayerNorm ----------------
__global__ void ln_kernel(const float* __restrict__ in, const float* __restrict__ g,
                          const float* __restrict__ b, float* __restrict__ out) {
    int w = (blockIdx.x * blockDim.x + threadIdx.x) >> 5;
    int lane = threadIdx.x & 31;
    if (w >= NN) return;
    const float* row = in + (size_t)w * 128;
    float v[4], s = 0.f;
#pragma unroll
    for (int j = 0; j < 4; j++) { v[j] = row[j * 32 + lane]; s += v[j]; }
#pragma unroll
    for (int off = 16; off > 0; off >>= 1) s += __shfl_xor_sync(0xffffffffu, s, off);
    float mean = s * (1.f / 128.f), s2 = 0.f;
#pragma unroll
    for (int j = 0; j < 4; j++) { float d = v[j] - mean; s2 += d * d; }
#pragma unroll
    for (int off = 16; off > 0; off >>= 1) s2 += __shfl_xor_sync(0xffffffffu, s2, off);
    float inv = rsqrtf(s2 * (1.f / 128.f) + 1e-12f);
#pragma unroll
    for (int j = 0; j < 4; j++) {
        int e = j * 32 + lane;
        out[(size_t)w * 128 + e] = g[e] * (v[j] - mean) * inv + b[e];
    }
}

// ---------------- GRU + LN3 ----------------
__global__ void gru_ln_kernel(const float* __restrict__ hprev,
                              const float* __restrict__ lng, const float* __restrict__ lnb) {
    int w = (blockIdx.x * blockDim.x + threadIdx.x) >> 5;
    int lane = threadIdx.x & 31;
    if (w >= NN) return;
    float hn[4], s = 0.f;
#pragma unroll
    for (int j = 0; j < 4; j++) {
        int e = j * 32 + lane;
        size_t b3 = (size_t)w * 384;
        float ir = g_gi[b3 + e], iz = g_gi[b3 + 128 + e], in_ = g_gi[b3 + 256 + e];
        float hr = g_gh[b3 + e], hz = g_gh[b3 + 128 + e], hnn = g_gh[b3 + 256 + e];
        float hv = hprev[(size_t)w * 128 + e];
        float r = 1.f / (1.f + expf(-(ir + hr)));
        float z = 1.f / (1.f + expf(-(iz + hz)));
        float n = tanhf(in_ + r * hnn);
        float hnew = (1.f - z) * n + z * hv;
        g_h[(size_t)w * 128 + e] = hnew;
        hn[j] = hnew;
        s += hnew;
    }
#pragma unroll
    for (int off = 16; off > 0; off >>= 1) s += __shfl_xor_sync(0xffffffffu, s, off);
    float mean = s * (1.f / 128.f), s2 = 0.f;
#pragma unroll
    for (int j = 0; j < 4; j++) { float d = hn[j] - mean; s2 += d * d; }
#pragma unroll
    for (int off = 16; off > 0; off >>= 1) s2 += __shfl_xor_sync(0xffffffffu, s2, off);
    float inv = rsqrtf(s2 * (1.f / 128.f) + 1e-12f);
#pragma unroll
    for (int j = 0; j < 4; j++) {
        int e = j * 32 + lane;
        g_x[(size_t)w * 128 + e] = lng[e] * (hn[j] - mean) * inv + lnb[e];
    }
}

__global__ void copy4_kernel(float4* __restrict__ dst, const float4* __restrict__ src, int n) {
    int i = blockIdx.x * blockDim.x + threadIdx.x;
    if (i < n) dst[i] = src[i];
}

// ---------------- host ----------------
static void* sym_addr(const void* symbol) {
    void* p = nullptr;
    cudaGetSymbolAddress(&p, symbol);
    return p;
}

extern "C" void kernel_launch(void* const* d_in, const int* in_sizes, int n_in,
                              void* d_out, int out_size) {
    (void)in_sizes; (void)n_in; (void)out_size;
    const float* x     = (const float*)d_in[0];
    const int*   ei    = (const int*)d_in[1];
    const float* eattr = (const float*)d_in[2];
    const float* wq  = (const float*)d_in[3];  const float* bq  = (const float*)d_in[4];
    const float* wk  = (const float*)d_in[5];  const float* bk  = (const float*)d_in[6];
    const float* wv  = (const float*)d_in[7];  const float* bv  = (const float*)d_in[8];
    const float* wao = (const float*)d_in[9];  const float* bao = (const float*)d_in[10];
    const float* ln1g = (const float*)d_in[11]; const float* ln1b = (const float*)d_in[12];
    const float* wint = (const float*)d_in[13]; const float* bint = (const float*)d_in[14];
    const float* wout = (const float*)d_in[15]; const float* bout = (const float*)d_in[16];
    const float* ln2g = (const float*)d_in[17]; const float* ln2b = (const float*)d_in[18];
    const float* wih = (const float*)d_in[19];  const float* whh = (const float*)d_in[20];
    const float* bih = (const float*)d_in[21];  const float* bhh = (const float*)d_in[22];
    const float* ln3g = (const float*)d_in[23]; const float* ln3b = (const float*)d_in[24];
    float* out = (float*)d_out;

    float* pP    = (float*)sym_addr(g_P);
    float* pSxe  = (float*)sym_addr(g_sxe);
    float* pPre  = (float*)sym_addr(g_pre);
    float* pAtt  = (float*)sym_addr(g_att);
    float* pInt  = (float*)sym_addr(g_inter);
    float* pM    = (float*)sym_addr(g_m);
    float* pH    = (float*)sym_addr(g_h);
    float* pX    = (float*)sym_addr(g_x);
    float* pGi   = (float*)sym_addr(g_gi);
    float* pGh   = (float*)sym_addr(g_gh);
    float* pBproj = (float*)sym_addr(g_bproj);
    float* pBav   = (float*)sym_addr(g_bav);
    float* pImg   = (float*)sym_addr(g_img);

    const int* srcp = ei;
    const int* dstp = ei + EE;

    const int SMB = 18432 * 4;  // 73728 B
    cudaFuncSetAttribute(gemm_tf<1>, cudaFuncAttributeMaxDynamicSharedMemorySize, SMB);
    cudaFuncSetAttribute(gemm_tf<2>, cudaFuncAttributeMaxDynamicSharedMemorySize, SMB);
    cudaFuncSetAttribute(gemm_tf<3>, cudaFuncAttributeMaxDynamicSharedMemorySize, SMB);

    // launches 1-5: prep + CSR (6th launch = proj GEMM, for ncu -s 5)
    build_all<<<(204736 + 255) / 256, 256>>>(wq, wk, wv, wao, bq, bk, bv, bao);
    prep_w_all<<<(393216 + 255) / 256, 256>>>(wint, wout, wih, whh);
    hist_kernel<<<(EE + 255) / 256, 256>>>(dstp);
    scan_kernel<<<1, 1024>>>();
    scatter_kernel<<<(EE + 255) / 256, 256>>>(srcp, dstp);

    const int MT = (NN + 127) / 128;   // 313
    const int RG = (NN + 7) / 8;

    for (int t = 0; t < 3; t++) {
        const float* xcur = (t == 0) ? x : pX;
        const float* hcur = (t == 0) ? x : pH;
        // proj: x @ [Wq|Wk|M]^T -> P (N x 768)
        gemm_tf<1><<<dim3(MT, 6), 256, SMB>>>(xcur, 128, pImg + (size_t)IMG_PROJ * 9216,
                                              pBproj, nullptr, pP, NN, 4, 768);
        gat2_kernel<<<RG, 256>>>(eattr, xcur);
        // fused attn-out: sxe @ Wav4^T + bav + x
        gemm_tf<2><<<dim3(MT, 1), 256, SMB>>>(pSxe, 512, pImg + (size_t)IMG_WAV4 * 9216,
                                              pBav, xcur, pPre, NN, 16, 128);
        ln_kernel<<<RG, 256>>>(pPre, ln1g, ln1b, pAtt);
        // FFN
        gemm_tf<3><<<dim3(MT, 4), 256, SMB>>>(pAtt, 128, pImg + (size_t)IMG_WINT * 9216,
                                              bint, nullptr, pInt, NN, 4, 512);
        gemm_tf<2><<<dim3(MT, 1), 256, SMB>>>(pInt, 512, pImg + (size_t)IMG_WOUT * 9216,
                                              bout, pAtt, pPre, NN, 16, 128);
        ln_kernel<<<RG, 256>>>(pPre, ln2g, ln2b, pM);
        // GRU
        gemm_tf<1><<<dim3(MT, 3), 256, SMB>>>(pM, 128, pImg + (size_t)IMG_WIH * 9216,
                                              bih, nullptr, pGi, NN, 4, 384);
        gemm_tf<1><<<dim3(MT, 3), 256, SMB>>>(hcur, 128, pImg + (size_t)IMG_WHH * 9216,
                                              bhh, nullptr, pGh, NN, 4, 384);
        gru_ln_kernel<<<RG, 256>>>(hcur, ln3g, ln3b);
    }

    copy4_kernel<<<(NN * 32 + 255) / 256, 256>>>((float4*)out, (const float4*)pX, NN * 32);
}

// round 6
// speedup vs baseline: 1.3378x; 1.3378x over previous
#include <cuda_runtime.h>
#include <cuda_bf16.h>
#include <math.h>
#include <stdint.h>

#define NN 40000
#define EE 320000

// ---------------- device scratch ----------------
__device__ float g_P[(size_t)NN * 768];
__device__ float g_sxe[(size_t)NN * 512];
__device__ float g_pre[NN * 128];
__device__ float g_att[NN * 128];
__device__ float g_inter[(size_t)NN * 512];
__device__ float g_m[NN * 128];
__device__ float g_h[NN * 128];
__device__ float g_x[NN * 128];
__device__ float g_gi[(size_t)NN * 384];
__device__ float g_gh[(size_t)NN * 384];
__device__ float g_WprojF[768 * 128];
__device__ float g_Wav4F[128 * 512];
__device__ float g_bproj[768];
__device__ float g_bav[128];
__device__ float g_wbv[128];    // Wao @ bv (empty-node correction)
// bf16 hi/lo weight chunk-images: each chunk-image = [hi 128x36 | lo 128x36] u32 = 9216 words
__device__ uint32_t g_img[(size_t)48 * 9216];
__device__ int g_cnt[NN], g_rowptr[NN + 1], g_cur[NN], g_srcs[EE], g_eidxs[EE];

// chunk-image offsets (units of 9216 u32)
#define IMG_PROJ 0
#define IMG_WAV4 12
#define IMG_WINT 20
#define IMG_WOUT 28
#define IMG_WIH  36
#define IMG_WHH  42

// ---------------- helpers ----------------
__device__ __forceinline__ void bf16_split2(float a, float b, uint32_t& hi, uint32_t& lo) {
    __nv_bfloat16 ha = __float2bfloat16(a), hb = __float2bfloat16(b);
    float ra = a - __bfloat162float(ha), rb = b - __bfloat162float(hb);
    __nv_bfloat16 la = __float2bfloat16(ra), lb = __float2bfloat16(rb);
    hi = (uint32_t)__bfloat16_as_ushort(ha) | ((uint32_t)__bfloat16_as_ushort(hb) << 16);
    lo = (uint32_t)__bfloat16_as_ushort(la) | ((uint32_t)__bfloat16_as_ushort(lb) << 16);
}
__device__ __forceinline__ void mma_bf16(float* d, const uint32_t* a, uint32_t b0, uint32_t b1) {
    asm volatile(
        "mma.sync.aligned.m16n8k16.row.col.f32.bf16.bf16.f32 "
        "{%0,%1,%2,%3}, {%4,%5,%6,%7}, {%8,%9}, {%0,%1,%2,%3};"
        : "+f"(d[0]), "+f"(d[1]), "+f"(d[2]), "+f"(d[3])
        : "r"(a[0]), "r"(a[1]), "r"(a[2]), "r"(a[3]), "r"(b0), "r"(b1));
}

// ---------------- fused prep #1 ----------------
__global__ void build_all(const float* __restrict__ wq, const float* __restrict__ wk,
                          const float* __restrict__ wv, const float* __restrict__ wao,
                          const float* __restrict__ bq, const float* __restrict__ bk,
                          const float* __restrict__ bv, const float* __restrict__ bao) {
    int idx = blockIdx.x * blockDim.x + threadIdx.x;
    const float SC = 0.17677669529663687f;
    if (idx < 98304) {                       // WprojF [768 x 128]
        int n = idx >> 7, k = idx & 127;
        float v;
        if (n < 128) v = wq[n * 128 + k] * SC;
        else if (n < 256) v = wk[(n - 128) * 128 + k];
        else {
            int h = (n - 256) >> 7, d1 = (n - 256) & 127;
            float s = 0.f;
            for (int r = 0; r < 32; r++)
                s += wk[(h * 32 + r) * 128 + d1] * wq[(h * 32 + r) * 128 + k];
            v = s * SC;
        }
        g_WprojF[idx] = v;
    } else if (idx < 163840) {               // Wav4F [128 x 512]
        int i2 = idx - 98304;
        int n = i2 >> 9, m = i2 & 511;
        int h = m >> 7, d = m & 127;
        float s = 0.f;
        for (int r = 0; r < 32; r++)
            s += wao[n * 128 + h * 32 + r] * wv[(h * 32 + r) * 128 + d];
        g_Wav4F[i2] = s;
    } else if (idx < 164608) {               // bproj [768]
        int n = idx - 163840;
        float v;
        if (n < 128) v = bq[n] * SC;
        else if (n < 256) v = bk[n - 128];
        else {
            int h = (n - 256) >> 7, d1 = (n - 256) & 127;
            float s = 0.f;
            for (int r = 0; r < 32; r++)
                s += wk[(h * 32 + r) * 128 + d1] * bq[h * 32 + r];
            v = s * SC;
        }
        g_bproj[n] = v;
    } else if (idx < 164736) {               // bav / wbv [128]
        int n = idx - 164608;
        float s = 0.f;
        for (int k = 0; k < 128; k++) s += wao[n * 128 + k] * bv[k];
        g_wbv[n] = s;
        g_bav[n] = s + bao[n];
    } else if (idx < 204736) {               // zero cnt
        g_cnt[idx - 164736] = 0;
    }
}

// ---------------- fused prep #2: weights -> bf16 hi/lo chunk-images ----------------
__device__ __forceinline__ void img_write(const float* src, int i2, int K, int base) {
    int n = i2 / K, k = i2 % K;
    float v = src[i2];
    __nv_bfloat16 h = __float2bfloat16(v);
    __nv_bfloat16 l = __float2bfloat16(v - __bfloat162float(h));
    int KC = K >> 6;
    size_t im = (size_t)(base + (n >> 7) * KC + (k >> 6));
    size_t word = im * 9216 + (n & 127) * 36 + ((k & 63) >> 1);
    unsigned short* p = (unsigned short*)g_img;
    p[word * 2 + (k & 1)] = __bfloat16_as_ushort(h);
    p[(word + 4608) * 2 + (k & 1)] = __bfloat16_as_ushort(l);
}
__global__ void prep_w_all(const float* __restrict__ wint, const float* __restrict__ wout,
                           const float* __restrict__ wih, const float* __restrict__ whh) {
    int idx = blockIdx.x * blockDim.x + threadIdx.x;
    if (idx < 98304)       img_write(g_WprojF, idx, 128, IMG_PROJ);
    else if (idx < 163840) img_write(g_Wav4F, idx - 98304, 512, IMG_WAV4);
    else if (idx < 229376) img_write(wint, idx - 163840, 128, IMG_WINT);
    else if (idx < 294912) img_write(wout, idx - 229376, 512, IMG_WOUT);
    else if (idx < 344064) img_write(wih, idx - 294912, 128, IMG_WIH);
    else if (idx < 393216) img_write(whh, idx - 344064, 128, IMG_WHH);
}

// ---------------- CSR build ----------------
__global__ void hist_kernel(const int* __restrict__ dst) {
    int i = blockIdx.x * blockDim.x + threadIdx.x;
    if (i < EE) atomicAdd(&g_cnt[dst[i]], 1);
}
// 1024-thread block scan (shuffle-based)
__global__ void scan_kernel() {
    __shared__ int wsum[32];
    int t = threadIdx.x;
    const int per = 40;
    int base = t * per;
    int s = 0;
    for (int i = 0; i < per; i++) {
        int idx = base + i;
        if (idx < NN) s += g_cnt[idx];
    }
    int lane = t & 31, wid = t >> 5;
    int v = s;
#pragma unroll
    for (int off = 1; off < 32; off <<= 1) {
        int n = __shfl_up_sync(0xffffffffu, v, off);
        if (lane >= off) v += n;
    }
    if (lane == 31) wsum[wid] = v;
    __syncthreads();
    if (wid == 0) {
        int w = wsum[lane];
#pragma unroll
        for (int off = 1; off < 32; off <<= 1) {
            int n = __shfl_up_sync(0xffffffffu, w, off);
            if (lane >= off) w += n;
        }
        wsum[lane] = w;
    }
    __syncthreads();
    int excl = v - s + (wid > 0 ? wsum[wid - 1] : 0);
    int r = excl;
    for (int i = 0; i < per; i++) {
        int idx = base + i;
        if (idx < NN) {
            g_rowptr[idx] = r;
            g_cur[idx] = r;
            r += g_cnt[idx];
        }
    }
    if (t == 1023) g_rowptr[NN] = r;
}
__global__ void scatter_kernel(const int* __restrict__ src, const int* __restrict__ dst) {
    int i = blockIdx.x * blockDim.x + threadIdx.x;
    if (i >= EE) return;
    int d = dst[i];
    int p = atomicAdd(&g_cur[d], 1);
    g_srcs[p] = src[i];
    g_eidxs[p] = i;
}

// ---------------- bf16 3-term mma GEMM, 2 CTAs/SM ----------------
// C[M, gridDim.y*128] = A[M,lda] @ W^T. K-chunk=64. smem 73728B.
// EPI: 1 bias, 2 bias+residual, 3 bias+gelu
template <int EPI>
__global__ void __launch_bounds__(256, 2) gemm_bf16(
    const float* __restrict__ A, int lda,
    const uint32_t* __restrict__ img,
    const float* __restrict__ bias, const float* __restrict__ res,
    float* __restrict__ out, int M, int KC, int ldo)
{
    extern __shared__ uint32_t smw[];
    uint32_t* AhS = smw;             // 4608
    uint32_t* AlS = smw + 4608;      // 4608
    uint32_t* BS  = smw + 9216;      // 9216 = [hi 4608 | lo 4608]

    const int tid = threadIdx.x;
    const int warp = tid >> 5, lane = tid & 31;
    const int wm = warp >> 1, wn = warp & 1;
    const int lr = lane >> 2, lk = lane & 3;
    const int bm = blockIdx.x * 128;

    float acc[2][8][4];
#pragma unroll
    for (int i = 0; i < 2; i++)
#pragma unroll
        for (int j = 0; j < 8; j++)
#pragma unroll
            for (int l = 0; l < 4; l++) acc[i][j][l] = 0.f;

    int gr = bm + (tid >> 1);
    if (gr >= M) gr = M - 1;
    const float* asrc = A + (size_t)gr * lda + (tid & 1) * 32;
    uint32_t* dh = AhS + (tid >> 1) * 36 + (tid & 1) * 16;
    uint32_t* dl = AlS + (tid >> 1) * 36 + (tid & 1) * 16;
    const uint4* bimg = (const uint4*)(img + (size_t)blockIdx.y * KC * 9216);

    for (int c = 0; c < KC; c++) {
        // A fill: 32 fp32 -> 16 u32 hi + 16 u32 lo
        const float* s0 = asrc + c * 64;
#pragma unroll
        for (int p = 0; p < 16; p += 2) {
            float4 f = *(const float4*)(s0 + 2 * p);
            uint32_t h0, l0, h1, l1;
            bf16_split2(f.x, f.y, h0, l0);
            bf16_split2(f.z, f.w, h1, l1);
            dh[p] = h0; dh[p + 1] = h1;
            dl[p] = l0; dl[p + 1] = l1;
        }
        // B fill: 9 uint4 per thread from pre-swizzled chunk image
        {
            const uint4* bsrc4 = bimg + (size_t)c * 2304;
#pragma unroll
            for (int j = 0; j < 9; j++)
                *(uint4*)(BS + (j * 256 + tid) * 4) = bsrc4[j * 256 + tid];
        }
        __syncthreads();

#pragma unroll
        for (int s = 0; s < 4; s++) {
            const int akp = s * 8 + lk;
            uint32_t ah[2][4], al[2][4];
#pragma unroll
            for (int mt = 0; mt < 2; mt++) {
                int rb = (wm * 32 + mt * 16 + lr) * 36 + akp;
                ah[mt][0] = AhS[rb];       ah[mt][1] = AhS[rb + 288];
                ah[mt][2] = AhS[rb + 4];   ah[mt][3] = AhS[rb + 292];
                al[mt][0] = AlS[rb];       al[mt][1] = AlS[rb + 288];
                al[mt][2] = AlS[rb + 4];   al[mt][3] = AlS[rb + 292];
            }
#pragma unroll
            for (int nt = 0; nt < 8; nt++) {
                int nb = (wn * 64 + nt * 8 + lr) * 36 + akp;
                uint32_t bh0 = BS[nb], bh1 = BS[nb + 4];
                uint32_t bl0 = BS[4608 + nb], bl1 = BS[4608 + nb + 4];
#pragma unroll
                for (int mt = 0; mt < 2; mt++) {
                    mma_bf16(acc[mt][nt], ah[mt], bh0, bh1);
                    mma_bf16(acc[mt][nt], ah[mt], bl0, bl1);
                    mma_bf16(acc[mt][nt], al[mt], bh0, bh1);
                }
            }
        }
        __syncthreads();
    }

    // epilogue
    const int cbase = blockIdx.y * 128 + wn * 64;
#pragma unroll
    for (int mt = 0; mt < 2; mt++) {
        int r0 = bm + wm * 32 + mt * 16 + lr;
#pragma unroll
        for (int half = 0; half < 2; half++) {
            int row = r0 + half * 8;
            if (row >= M) continue;
            float* orow = out + (size_t)row * ldo + cbase;
            const float* rrow = (EPI == 2) ? (res + (size_t)row * ldo + cbase) : nullptr;
#pragma unroll
            for (int nt = 0; nt < 8; nt++) {
                int cl = nt * 8 + lk * 2;
                float v0 = acc[mt][nt][half * 2 + 0];
                float v1 = acc[mt][nt][half * 2 + 1];
                v0 += bias[cbase + cl];
                v1 += bias[cbase + cl + 1];
                if (EPI == 2) { v0 += rrow[cl]; v1 += rrow[cl + 1]; }
                if (EPI == 3) {
                    v0 = 0.5f * v0 * (1.f + erff(v0 * 0.70710678118654752f));
                    v1 = 0.5f * v1 * (1.f + erff(v1 * 0.70710678118654752f));
                }
                *(float2*)(orow + cl) = make_float2(v0, v1);
            }
        }
    }
}

// ---------------- GAT: warp per node, per-head online softmax ----------------
__global__ void gat2_kernel(const float* __restrict__ eattr, const float* __restrict__ xsrc) {
    int w = (blockIdx.x * blockDim.x + threadIdx.x) >> 5;
    int lane = threadIdx.x & 31;
    if (w >= NN) return;
    float q[4], qe[4][4], mx[4], smx[4], acc[4][4];
    const float* Pw = g_P + (size_t)w * 768;
#pragma unroll
    for (int j = 0; j < 4; j++) q[j] = Pw[j * 32 + lane];
#pragma unroll
    for (int h = 0; h < 4; h++) {
#pragma unroll
        for (int j = 0; j < 4; j++) {
            qe[h][j] = Pw[256 + h * 128 + j * 32 + lane];
            acc[h][j] = 0.f;
        }
        mx[h] = -1e30f; smx[h] = 0.f;
    }
    int beg = g_rowptr[w], end = g_rowptr[w + 1];
    for (int p = beg; p < end; p++) {
        int s = g_srcs[p], ei = g_eidxs[p];
        const float* kp = g_P + (size_t)s * 768 + 128;
        const float* xp = xsrc + (size_t)s * 128;
        const float* ep = eattr + (size_t)ei * 128;
        float ks[4], ev[4], u[4];
#pragma unroll
        for (int j = 0; j < 4; j++) {
            ks[j] = kp[j * 32 + lane];
            ev[j] = ep[j * 32 + lane];
            u[j] = xp[j * 32 + lane] + ev[j];
        }
        float d[4];
#pragma unroll
        for (int h = 0; h < 4; h++)
            d[h] = q[h] * ks[h] + qe[h][0] * ev[0] + qe[h][1] * ev[1]
                 + qe[h][2] * ev[2] + qe[h][3] * ev[3];
#pragma unroll
        for (int off = 16; off > 0; off >>= 1)
#pragma unroll
            for (int h = 0; h < 4; h++)
                d[h] += __shfl_xor_sync(0xffffffffu, d[h], off);
#pragma unroll
        for (int h = 0; h < 4; h++) {
            float a = d[h];
            float nm = fmaxf(mx[h], a);
            float csc = __expf(mx[h] - nm);
            float pe = __expf(a - nm);
            smx[h] = smx[h] * csc + pe;
#pragma unroll
            for (int j = 0; j < 4; j++)
                acc[h][j] = acc[h][j] * csc + pe * u[j];
            mx[h] = nm;
        }
    }
    float* o = g_sxe + (size_t)w * 512;
#pragma unroll
    for (int h = 0; h < 4; h++) {
        float inv = 1.f / (smx[h] + 1e-16f);
#pragma unroll
        for (int j = 0; j < 4; j++)
            o[h * 128 + j * 32 + lane] = acc[h][j] * inv;
    }
}

// ---------------- LayerNorm (optional empty-node correction) ----------------
__global__ void ln_kernel(const float* __restrict__ in, const float* __restrict__ g,
                          const float* __restrict__ b, const float* __restrict__ corr,
                          float* __restrict__ out) {
    int w = (blockIdx.x * blockDim.x + threadIdx.x) >> 5;
    int lane = threadIdx.x & 31;
    if (w >= NN) return;
    bool empty = false;
    if (corr) empty = (g_rowptr[w] == g_rowptr[w + 1]);
    const float* row = in + (size_t)w * 128;
    float v[4], s = 0.f;
#pragma unroll
    for (int j = 0; j < 4; j++) {
        int e = j * 32 + lane;
        v[j] = row[e];
        if (empty) v[j] -= corr[e];
        s += v[j];
    }
#pragma unroll
    for (int off = 16; off > 0; off >>= 1) s += __shfl_xor_sync(0xffffffffu, s, off);
    float mean = s * (1.f / 128.f), s2 = 0.f;
#pragma unroll
    for (int j = 0; j < 4; j++) { float d = v[j] - mean; s2 += d * d; }
#pragma unroll
    for (int off = 16; off > 0; off >>= 1) s2 += __shfl_xor_sync(0xffffffffu, s2, off);
    float inv = rsqrtf(s2 * (1.f / 128.f) + 1e-12f);
#pragma unroll
    for (int j = 0; j < 4; j++) {
        int e = j * 32 + lane;
        out[(size_t)w * 128 + e] = g[e] * (v[j] - mean) * inv + b[e];
    }
}

// ---------------- GRU + LN3 ----------------
__global__ void gru_ln_kernel(const float* __restrict__ hprev,
                              const float* __restrict__ lng, const float* __restrict__ lnb,
                              float* __restrict__ xout) {
    int w = (blockIdx.x * blockDim.x + threadIdx.x) >> 5;
    int lane = threadIdx.x & 31;
    if (w >= NN) return;
    float hn[4], s = 0.f;
#pragma unroll
    for (int j = 0; j < 4; j++) {
        int e = j * 32 + lane;
        size_t b3 = (size_t)w * 384;
        float ir = g_gi[b3 + e], iz = g_gi[b3 + 128 + e], in_ = g_gi[b3 + 256 + e];
        float hr = g_gh[b3 + e], hz = g_gh[b3 + 128 + e], hnn = g_gh[b3 + 256 + e];
        float hv = hprev[(size_t)w * 128 + e];
        float r = 1.f / (1.f + expf(-(ir + hr)));
        float z = 1.f / (1.f + expf(-(iz + hz)));
        float n = tanhf(in_ + r * hnn);
        float hnew = (1.f - z) * n + z * hv;
        g_h[(size_t)w * 128 + e] = hnew;
        hn[j] = hnew;
        s += hnew;
    }
#pragma unroll
    for (int off = 16; off > 0; off >>= 1) s += __shfl_xor_sync(0xffffffffu, s, off);
    float mean = s * (1.f / 128.f), s2 = 0.f;
#pragma unroll
    for (int j = 0; j < 4; j++) { float d = hn[j] - mean; s2 += d * d; }
#pragma unroll
    for (int off = 16; off > 0; off >>= 1) s2 += __shfl_xor_sync(0xffffffffu, s2, off);
    float inv = rsqrtf(s2 * (1.f / 128.f) + 1e-12f);
#pragma unroll
    for (int j = 0; j < 4; j++) {
        int e = j * 32 + lane;
        xout[(size_t)w * 128 + e] = lng[e] * (hn[j] - mean) * inv + lnb[e];
    }
}

// ---------------- host ----------------
static void* sym_addr(const void* symbol) {
    void* p = nullptr;
    cudaGetSymbolAddress(&p, symbol);
    return p;
}

extern "C" void kernel_launch(void* const* d_in, const int* in_sizes, int n_in,
                              void* d_out, int out_size) {
    (void)in_sizes; (void)n_in; (void)out_size;
    const float* x     = (const float*)d_in[0];
    const int*   ei    = (const int*)d_in[1];
    const float* eattr = (const float*)d_in[2];
    const float* wq  = (const float*)d_in[3];  const float* bq  = (const float*)d_in[4];
    const float* wk  = (const float*)d_in[5];  const float* bk  = (const float*)d_in[6];
    const float* wv  = (const float*)d_in[7];  const float* bv  = (const float*)d_in[8];
    const float* wao = (const float*)d_in[9];  const float* bao = (const float*)d_in[10];
    const float* ln1g = (const float*)d_in[11]; const float* ln1b = (const float*)d_in[12];
    const float* wint = (const float*)d_in[13]; const float* bint = (const float*)d_in[14];
    const float* wout = (const float*)d_in[15]; const float* bout = (const float*)d_in[16];
    const float* ln2g = (const float*)d_in[17]; const float* ln2b = (const float*)d_in[18];
    const float* wih = (const float*)d_in[19];  const float* whh = (const float*)d_in[20];
    const float* bih = (const float*)d_in[21];  const float* bhh = (const float*)d_in[22];
    const float* ln3g = (const float*)d_in[23]; const float* ln3b = (const float*)d_in[24];
    float* out = (float*)d_out;

    float* pP    = (float*)sym_addr(g_P);
    float* pSxe  = (float*)sym_addr(g_sxe);
    float* pPre  = (float*)sym_addr(g_pre);
    float* pAtt  = (float*)sym_addr(g_att);
    float* pInt  = (float*)sym_addr(g_inter);
    float* pM    = (float*)sym_addr(g_m);
    float* pH    = (float*)sym_addr(g_h);
    float* pX    = (float*)sym_addr(g_x);
    float* pGi   = (float*)sym_addr(g_gi);
    float* pGh   = (float*)sym_addr(g_gh);
    float* pBproj = (float*)sym_addr(g_bproj);
    float* pBav   = (float*)sym_addr(g_bav);
    float* pWbv   = (float*)sym_addr(g_wbv);
    uint32_t* pImg = (uint32_t*)sym_addr(g_img);

    const int* srcp = ei;
    const int* dstp = ei + EE;

    const int SMB = 18432 * 4;  // 73728 B
    cudaFuncSetAttribute(gemm_bf16<1>, cudaFuncAttributeMaxDynamicSharedMemorySize, SMB);
    cudaFuncSetAttribute(gemm_bf16<2>, cudaFuncAttributeMaxDynamicSharedMemorySize, SMB);
    cudaFuncSetAttribute(gemm_bf16<3>, cudaFuncAttributeMaxDynamicSharedMemorySize, SMB);

    // launches 1-5: prep + CSR (6th launch = proj GEMM, for ncu -s 5)
    build_all<<<(204736 + 255) / 256, 256>>>(wq, wk, wv, wao, bq, bk, bv, bao);
    prep_w_all<<<(393216 + 255) / 256, 256>>>(wint, wout, wih, whh);
    hist_kernel<<<(EE + 255) / 256, 256>>>(dstp);
    scan_kernel<<<1, 1024>>>();
    scatter_kernel<<<(EE + 255) / 256, 256>>>(srcp, dstp);

    const int MT = (NN + 127) / 128;   // 313
    const int RG = (NN + 7) / 8;

    for (int t = 0; t < 3; t++) {
        const float* xcur = (t == 0) ? x : pX;
        const float* hcur = (t == 0) ? x : pH;
        // proj: x @ [Wq|Wk|M]^T -> P (N x 768)
        gemm_bf16<1><<<dim3(MT, 6), 256, SMB>>>(xcur, 128, pImg + (size_t)IMG_PROJ * 9216,
                                                pBproj, nullptr, pP, NN, 2, 768);
        gat2_kernel<<<RG, 256>>>(eattr, xcur);
        // fused attn-out: sxe @ Wav4^T + bav + x
        gemm_bf16<2><<<dim3(MT, 1), 256, SMB>>>(pSxe, 512, pImg + (size_t)IMG_WAV4 * 9216,
                                                pBav, xcur, pPre, NN, 8, 128);
        ln_kernel<<<RG, 256>>>(pPre, ln1g, ln1b, pWbv, pAtt);
        // FFN
        gemm_bf16<3><<<dim3(MT, 4), 256, SMB>>>(pAtt, 128, pImg + (size_t)IMG_WINT * 9216,
                                                bint, nullptr, pInt, NN, 2, 512);
        gemm_bf16<2><<<dim3(MT, 1), 256, SMB>>>(pInt, 512, pImg + (size_t)IMG_WOUT * 9216,
                                                bout, pAtt, pPre, NN, 8, 128);
        ln_kernel<<<RG, 256>>>(pPre, ln2g, ln2b, nullptr, pM);
        // GRU
        gemm_bf16<1><<<dim3(MT, 3), 256, SMB>>>(pM, 128, pImg + (size_t)IMG_WIH * 9216,
                                                bih, nullptr, pGi, NN, 2, 384);
        gemm_bf16<1><<<dim3(MT, 3), 256, SMB>>>(hcur, 128, pImg + (size_t)IMG_WHH * 9216,
                                                bhh, nullptr, pGh, NN, 2, 384);
        gru_ln_kernel<<<RG, 256>>>(hcur, ln3g, ln3b, (t == 2) ? out : pX);
    }
}

// round 7
// speedup vs baseline: 1.4763x; 1.1035x over previous
#include <cuda_runtime.h>
#include <cuda_bf16.h>
#include <math.h>
#include <stdint.h>

#define NN 40000
#define EE 320000

// ---------------- device scratch ----------------
__device__ float g_P[(size_t)NN * 768];
__device__ float g_sxe[(size_t)NN * 512];
__device__ float g_pre[NN * 128];
__device__ float g_att[NN * 128];
__device__ float g_inter[(size_t)NN * 512];
__device__ float g_m[NN * 128];
__device__ float g_h[NN * 128];
__device__ float g_x[NN * 128];
__device__ float g_gi[(size_t)NN * 384];
__device__ float g_gh[(size_t)NN * 384];
// bf16 hi/lo packed activation planes (word j = elems 2j|2j+1; low16 = even elem)
__device__ uint32_t g_xH[NN * 64],  g_xL[NN * 64];
__device__ uint32_t g_hH[NN * 64],  g_hL[NN * 64];
__device__ uint32_t g_attH[NN * 64], g_attL[NN * 64];
__device__ uint32_t g_mH[NN * 64],  g_mL[NN * 64];
__device__ uint32_t g_intH[(size_t)NN * 256], g_intL[(size_t)NN * 256];
__device__ float g_WprojF[768 * 128];
__device__ float g_Wav4F[128 * 512];
__device__ float g_bproj[768];
__device__ float g_bav[128];
__device__ float g_wbv[128];
// bf16 hi/lo weight chunk-images: each = [hi 128x36 | lo 128x36] u32 = 9216 words
__device__ uint32_t g_img[(size_t)48 * 9216];
__device__ int g_cnt[NN], g_rowptr[NN + 1], g_cur[NN], g_srcs[EE], g_eidxs[EE];

#define IMG_PROJ 0
#define IMG_WAV4 12
#define IMG_WINT 20
#define IMG_WOUT 28
#define IMG_WIH  36
#define IMG_WHH  42

// ---------------- helpers ----------------
__device__ __forceinline__ void bf16_split2(float a, float b, uint32_t& hi, uint32_t& lo) {
    __nv_bfloat16 ha = __float2bfloat16(a), hb = __float2bfloat16(b);
    float ra = a - __bfloat162float(ha), rb = b - __bfloat162float(hb);
    __nv_bfloat16 la = __float2bfloat16(ra), lb = __float2bfloat16(rb);
    hi = (uint32_t)__bfloat16_as_ushort(ha) | ((uint32_t)__bfloat16_as_ushort(hb) << 16);
    lo = (uint32_t)__bfloat16_as_ushort(la) | ((uint32_t)__bfloat16_as_ushort(lb) << 16);
}
__device__ __forceinline__ void mma_bf16(float* d, const uint32_t* a, uint32_t b0, uint32_t b1) {
    asm volatile(
        "mma.sync.aligned.m16n8k16.row.col.f32.bf16.bf16.f32 "
        "{%0,%1,%2,%3}, {%4,%5,%6,%7}, {%8,%9}, {%0,%1,%2,%3};"
        : "+f"(d[0]), "+f"(d[1]), "+f"(d[2]), "+f"(d[3])
        : "r"(a[0]), "r"(a[1]), "r"(a[2]), "r"(a[3]), "r"(b0), "r"(b1));
}
__device__ __forceinline__ void ldm_x4(uint32_t* r, uint32_t addr) {
    asm volatile("ldmatrix.sync.aligned.m8n8.x4.shared.b16 {%0,%1,%2,%3}, [%4];"
                 : "=r"(r[0]), "=r"(r[1]), "=r"(r[2]), "=r"(r[3]) : "r"(addr));
}
__device__ __forceinline__ uint32_t smem_u32p(const void* p) {
    uint32_t a;
    asm("{ .reg .u64 t; cvta.to.shared.u64 t, %1; cvt.u32.u64 %0, t; }" : "=r"(a) : "l"(p));
    return a;
}

// ---------------- fused prep #1 ----------------
__global__ void build_all(const float* __restrict__ wq, const float* __restrict__ wk,
                          const float* __restrict__ wv, const float* __restrict__ wao,
                          const float* __restrict__ bq, const float* __restrict__ bk,
                          const float* __restrict__ bv, const float* __restrict__ bao) {
    int idx = blockIdx.x * blockDim.x + threadIdx.x;
    const float SC = 0.17677669529663687f;
    if (idx < 98304) {
        int n = idx >> 7, k = idx & 127;
        float v;
        if (n < 128) v = wq[n * 128 + k] * SC;
        else if (n < 256) v = wk[(n - 128) * 128 + k];
        else {
            int h = (n - 256) >> 7, d1 = (n - 256) & 127;
            float s = 0.f;
            for (int r = 0; r < 32; r++)
                s += wk[(h * 32 + r) * 128 + d1] * wq[(h * 32 + r) * 128 + k];
            v = s * SC;
        }
        g_WprojF[idx] = v;
    } else if (idx < 163840) {
        int i2 = idx - 98304;
        int n = i2 >> 9, m = i2 & 511;
        int h = m >> 7, d = m & 127;
        float s = 0.f;
        for (int r = 0; r < 32; r++)
            s += wao[n * 128 + h * 32 + r] * wv[(h * 32 + r) * 128 + d];
        g_Wav4F[i2] = s;
    } else if (idx < 164608) {
        int n = idx - 163840;
        float v;
        if (n < 128) v = bq[n] * SC;
        else if (n < 256) v = bk[n - 128];
        else {
            int h = (n - 256) >> 7, d1 = (n - 256) & 127;
            float s = 0.f;
            for (int r = 0; r < 32; r++)
                s += wk[(h * 32 + r) * 128 + d1] * bq[h * 32 + r];
            v = s * SC;
        }
        g_bproj[n] = v;
    } else if (idx < 164736) {
        int n = idx - 164608;
        float s = 0.f;
        for (int k = 0; k < 128; k++) s += wao[n * 128 + k] * bv[k];
        g_wbv[n] = s;
        g_bav[n] = s + bao[n];
    } else if (idx < 204736) {
        g_cnt[idx - 164736] = 0;
    }
}

// ---------------- fused prep #2: weights -> bf16 hi/lo chunk-images; also split x ----------------
__device__ __forceinline__ void img_write(const float* src, int i2, int K, int base) {
    int n = i2 / K, k = i2 % K;
    float v = src[i2];
    __nv_bfloat16 h = __float2bfloat16(v);
    __nv_bfloat16 l = __float2bfloat16(v - __bfloat162float(h));
    int KC = K >> 6;
    size_t im = (size_t)(base + (n >> 7) * KC + (k >> 6));
    size_t word = im * 9216 + (n & 127) * 36 + ((k & 63) >> 1);
    unsigned short* p = (unsigned short*)g_img;
    p[word * 2 + (k & 1)] = __bfloat16_as_ushort(h);
    p[(word + 4608) * 2 + (k & 1)] = __bfloat16_as_ushort(l);
}
__global__ void prep_w_all(const float* __restrict__ wint, const float* __restrict__ wout,
                           const float* __restrict__ wih, const float* __restrict__ whh) {
    int idx = blockIdx.x * blockDim.x + threadIdx.x;
    if (idx < 98304)       img_write(g_WprojF, idx, 128, IMG_PROJ);
    else if (idx < 163840) img_write(g_Wav4F, idx - 98304, 512, IMG_WAV4);
    else if (idx < 229376) img_write(wint, idx - 163840, 128, IMG_WINT);
    else if (idx < 294912) img_write(wout, idx - 229376, 512, IMG_WOUT);
    else if (idx < 344064) img_write(wih, idx - 294912, 128, IMG_WIH);
    else if (idx < 393216) img_write(whh, idx - 344064, 128, IMG_WHH);
}
__global__ void split_x_kernel(const float* __restrict__ x) {
    int i = blockIdx.x * blockDim.x + threadIdx.x;
    if (i >= NN * 64) return;
    float2 f = *(const float2*)(x + 2 * i);
    uint32_t hi, lo;
    bf16_split2(f.x, f.y, hi, lo);
    g_xH[i] = hi;
    g_xL[i] = lo;
}

// ---------------- CSR build ----------------
__global__ void hist_kernel(const int* __restrict__ dst) {
    int i = blockIdx.x * blockDim.x + threadIdx.x;
    if (i < EE) atomicAdd(&g_cnt[dst[i]], 1);
}
__global__ void scan_kernel() {
    extern __shared__ int sbuf[];   // 40960 ints
    __shared__ int wsum[32];
    int t = threadIdx.x;
    for (int i = 0; i < 40; i++) {
        int j = i * 1024 + t;
        sbuf[j] = (j < NN) ? g_cnt[j] : 0;
    }
    __syncthreads();
    int s = 0;
    for (int i = 0; i < 40; i++) s += sbuf[t * 40 + i];
    int lane = t & 31, wid = t >> 5;
    int v = s;
#pragma unroll
    for (int off = 1; off < 32; off <<= 1) {
        int n = __shfl_up_sync(0xffffffffu, v, off);
        if (lane >= off) v += n;
    }
    if (lane == 31) wsum[wid] = v;
    __syncthreads();
    if (wid == 0) {
        int w = wsum[lane];
#pragma unroll
        for (int off = 1; off < 32; off <<= 1) {
            int n = __shfl_up_sync(0xffffffffu, w, off);
            if (lane >= off) w += n;
        }
        wsum[lane] = w;
    }
    __syncthreads();
    int r = v - s + (wid > 0 ? wsum[wid - 1] : 0);
    for (int i = 0; i < 40; i++) {
        int tmp = sbuf[t * 40 + i];
        sbuf[t * 40 + i] = r;
        r += tmp;
    }
    __syncthreads();
    for (int i = 0; i < 40; i++) {
        int j = i * 1024 + t;
        if (j < NN) { g_rowptr[j] = sbuf[j]; g_cur[j] = sbuf[j]; }
    }
    if (t == 1023) g_rowptr[NN] = wsum[31];
}
__global__ void scatter_kernel(const int* __restrict__ src, const int* __restrict__ dst) {
    int i = blockIdx.x * blockDim.x + threadIdx.x;
    if (i >= EE) return;
    int d = dst[i];
    int p = atomicAdd(&g_cur[d], 1);
    g_srcs[p] = src[i];
    g_eidxs[p] = i;
}

// ---------------- bf16 3-term mma GEMM (ldmatrix + plane fills), 2 CTAs/SM ----------------
// ASPLIT: 1 = A given as hi/lo planes (AH/AL, width lda/2 u32); 0 = fp32 A with cvt fill
// WPL: 1 = also write hi/lo planes of output
template <int EPI, int ASPLIT, int WPL>
__global__ void __launch_bounds__(256, 2) gemm_bf16(
    const float* __restrict__ A, const uint32_t* __restrict__ AH, const uint32_t* __restrict__ AL,
    int lda, const uint32_t* __restrict__ img,
    const float* __restrict__ bias, const float* __restrict__ res,
    float* __restrict__ out, uint32_t* __restrict__ outH, uint32_t* __restrict__ outL,
    int M, int KC, int ldo)
{
    extern __shared__ uint32_t smw[];
    uint32_t* AhS = smw;             // 4608
    uint32_t* AlS = smw + 4608;      // 4608
    uint32_t* BS  = smw + 9216;      // 9216 = [hi | lo]

    const int tid = threadIdx.x;
    const int warp = tid >> 5, lane = tid & 31;
    const int wm = warp >> 1, wn = warp & 1;
    const int lr = lane >> 2, lk = lane & 3;
    const int bm = blockIdx.x * 128;

    float acc[2][8][4];
#pragma unroll
    for (int i = 0; i < 2; i++)
#pragma unroll
        for (int j = 0; j < 8; j++)
#pragma unroll
            for (int l = 0; l < 4; l++) acc[i][j][l] = 0.f;

    // ldmatrix lane addressing
    const uint32_t smb = smem_u32p(smw);
    const int a_row = ((lane >> 3) & 1) * 8 + (lane & 7);
    const int a_wrd = (lane >> 4) * 4;
    const uint32_t aAddr = smb + (uint32_t)(((wm * 32 + a_row) * 36 + a_wrd) * 4);
    const int b_row = ((lane >> 4) & 1) * 8 + (lane & 7);
    const int b_wrd = ((lane >> 3) & 1) * 4;
    const uint32_t bAddr = smb + 9216u * 4 + (uint32_t)(((wn * 64 + b_row) * 36 + b_wrd) * 4);

    // fill mapping
    int gr = bm + (tid >> 1);
    if (gr >= M) gr = M - 1;
    const int half = tid & 1;
    uint32_t* dh = AhS + (tid >> 1) * 36 + half * 16;
    uint32_t* dl = AlS + (tid >> 1) * 36 + half * 16;
    const float* asrc = ASPLIT ? nullptr : (A + (size_t)gr * lda + half * 32);
    const uint32_t* ahsrc = ASPLIT ? (AH + (size_t)gr * (lda >> 1) + half * 16) : nullptr;
    const uint32_t* alsrc = ASPLIT ? (AL + (size_t)gr * (lda >> 1) + half * 16) : nullptr;
    const uint4* bimg = (const uint4*)(img + (size_t)blockIdx.y * KC * 9216);

    for (int c = 0; c < KC; c++) {
        if (ASPLIT) {
            const uint4* sh4 = (const uint4*)(ahsrc + c * 32);
            const uint4* sl4 = (const uint4*)(alsrc + c * 32);
#pragma unroll
            for (int p = 0; p < 4; p++) {
                *(uint4*)(dh + p * 4) = sh4[p];
                *(uint4*)(dl + p * 4) = sl4[p];
            }
        } else {
            const float* s0 = asrc + c * 64;
#pragma unroll
            for (int p = 0; p < 16; p += 2) {
                float4 f = *(const float4*)(s0 + 2 * p);
                uint32_t h0, l0, h1, l1;
                bf16_split2(f.x, f.y, h0, l0);
                bf16_split2(f.z, f.w, h1, l1);
                dh[p] = h0; dh[p + 1] = h1;
                dl[p] = l0; dl[p + 1] = l1;
            }
        }
        {
            const uint4* bsrc4 = bimg + (size_t)c * 2304;
#pragma unroll
            for (int j = 0; j < 9; j++)
                *(uint4*)(BS + (j * 256 + tid) * 4) = bsrc4[j * 256 + tid];
        }
        __syncthreads();

#pragma unroll
        for (int s = 0; s < 4; s++) {
            uint32_t ah[2][4], al[2][4];
            ldm_x4(ah[0], aAddr + (0 * 576 + s * 8) * 4);
            ldm_x4(ah[1], aAddr + (1 * 576 + s * 8) * 4);
            ldm_x4(al[0], aAddr + 4608u * 4 + (0 * 576 + s * 8) * 4);
            ldm_x4(al[1], aAddr + 4608u * 4 + (1 * 576 + s * 8) * 4);
#pragma unroll
            for (int ntp = 0; ntp < 4; ntp++) {
                uint32_t bh[4], bl[4];
                ldm_x4(bh, bAddr + (ntp * 576 + s * 8) * 4);
                ldm_x4(bl, bAddr + 4608u * 4 + (ntp * 576 + s * 8) * 4);
#pragma unroll
                for (int hf = 0; hf < 2; hf++) {
                    int nt = ntp * 2 + hf;
#pragma unroll
                    for (int mt = 0; mt < 2; mt++) {
                        mma_bf16(acc[mt][nt], ah[mt], bh[2 * hf], bh[2 * hf + 1]);
                        mma_bf16(acc[mt][nt], ah[mt], bl[2 * hf], bl[2 * hf + 1]);
                        mma_bf16(acc[mt][nt], al[mt], bh[2 * hf], bh[2 * hf + 1]);
                    }
                }
            }
        }
        __syncthreads();
    }

    // epilogue
    const int cbase = blockIdx.y * 128 + wn * 64;
#pragma unroll
    for (int mt = 0; mt < 2; mt++) {
        int r0 = bm + wm * 32 + mt * 16 + lr;
#pragma unroll
        for (int hf = 0; hf < 2; hf++) {
            int row = r0 + hf * 8;
            if (row >= M) continue;
            float* orow = out + (size_t)row * ldo + cbase;
            const float* rrow = (EPI == 2) ? (res + (size_t)row * ldo + cbase) : nullptr;
#pragma unroll
            for (int nt = 0; nt < 8; nt++) {
                int cl = nt * 8 + lk * 2;
                float v0 = acc[mt][nt][hf * 2 + 0];
                float v1 = acc[mt][nt][hf * 2 + 1];
                v0 += bias[cbase + cl];
                v1 += bias[cbase + cl + 1];
                if (EPI == 2) { v0 += rrow[cl]; v1 += rrow[cl + 1]; }
                if (EPI == 3) {
                    v0 = 0.5f * v0 * (1.f + erff(v0 * 0.70710678118654752f));
                    v1 = 0.5f * v1 * (1.f + erff(v1 * 0.70710678118654752f));
                }
                *(float2*)(orow + cl) = make_float2(v0, v1);
                if (WPL) {
                    uint32_t hi, lo;
                    bf16_split2(v0, v1, hi, lo);
                    size_t pw = (size_t)row * (ldo >> 1) + ((cbase + cl) >> 1);
                    outH[pw] = hi;
                    outL[pw] = lo;
                }
            }
        }
    }
}

// ---------------- GAT ----------------
__global__ void gat2_kernel(const float* __restrict__ eattr, const float* __restrict__ xsrc) {
    int w = (blockIdx.x * blockDim.x + threadIdx.x) >> 5;
    int lane = threadIdx.x & 31;
    if (w >= NN) return;
    float q[4], qe[4][4], mx[4], smx[4], acc[4][4];
    const float* Pw = g_P + (size_t)w * 768;
#pragma unroll
    for (int j = 0; j < 4; j++) q[j] = Pw[j * 32 + lane];
#pragma unroll
    for (int h = 0; h < 4; h++) {
#pragma unroll
        for (int j = 0; j < 4; j++) {
            qe[h][j] = Pw[256 + h * 128 + j * 32 + lane];
            acc[h][j] = 0.f;
        }
        mx[h] = -1e30f; smx[h] = 0.f;
    }
    int beg = g_rowptr[w], end = g_rowptr[w + 1];
    for (int p = beg; p < end; p++) {
        int s = g_srcs[p], ei = g_eidxs[p];
        const float* kp = g_P + (size_t)s * 768 + 128;
        const float* xp = xsrc + (size_t)s * 128;
        const float* ep = eattr + (size_t)ei * 128;
        float ks[4], ev[4], u[4];
#pragma unroll
        for (int j = 0; j < 4; j++) {
            ks[j] = kp[j * 32 + lane];
            ev[j] = ep[j * 32 + lane];
            u[j] = xp[j * 32 + lane] + ev[j];
        }
        float d[4];
#pragma unroll
        for (int h = 0; h < 4; h++)
            d[h] = q[h] * ks[h] + qe[h][0] * ev[0] + qe[h][1] * ev[1]
                 + qe[h][2] * ev[2] + qe[h][3] * ev[3];
#pragma unroll
        for (int off = 16; off > 0; off >>= 1)
#pragma unroll
            for (int h = 0; h < 4; h++)
                d[h] += __shfl_xor_sync(0xffffffffu, d[h], off);
#pragma unroll
        for (int h = 0; h < 4; h++) {
            float a = d[h];
            float nm = fmaxf(mx[h], a);
            float csc = __expf(mx[h] - nm);
            float pe = __expf(a - nm);
            smx[h] = smx[h] * csc + pe;
#pragma unroll
            for (int j = 0; j < 4; j++)
                acc[h][j] = acc[h][j] * csc + pe * u[j];
            mx[h] = nm;
        }
    }
    float* o = g_sxe + (size_t)w * 512;
#pragma unroll
    for (int h = 0; h < 4; h++) {
        float inv = 1.f / (smx[h] + 1e-16f);
#pragma unroll
        for (int j = 0; j < 4; j++)
            o[h * 128 + j * 32 + lane] = acc[h][j] * inv;
    }
}

// ---------------- LayerNorm (writes fp32 + planes) ----------------
__global__ void ln_kernel(const float* __restrict__ in, const float* __restrict__ g,
                          const float* __restrict__ b, const float* __restrict__ corr,
                          float* __restrict__ out, uint32_t* __restrict__ oH,
                          uint32_t* __restrict__ oL) {
    int w = (blockIdx.x * blockDim.x + threadIdx.x) >> 5;
    int lane = threadIdx.x & 31;
    if (w >= NN) return;
    const float* row = in + (size_t)w * 128;
    float4 v4 = *(const float4*)(row + lane * 4);
    float v[4] = {v4.x, v4.y, v4.z, v4.w};
    if (corr && g_rowptr[w] == g_rowptr[w + 1]) {
        float4 c4 = *(const float4*)(corr + lane * 4);
        v[0] -= c4.x; v[1] -= c4.y; v[2] -= c4.z; v[3] -= c4.w;
    }
    float s = v[0] + v[1] + v[2] + v[3];
#pragma unroll
    for (int off = 16; off > 0; off >>= 1) s += __shfl_xor_sync(0xffffffffu, s, off);
    float mean = s * (1.f / 128.f), s2 = 0.f;
#pragma unroll
    for (int j = 0; j < 4; j++) { float d = v[j] - mean; s2 += d * d; }
#pragma unroll
    for (int off = 16; off > 0; off >>= 1) s2 += __shfl_xor_sync(0xffffffffu, s2, off);
    float inv = rsqrtf(s2 * (1.f / 128.f) + 1e-12f);
    float4 g4 = *(const float4*)(g + lane * 4);
    float4 b4 = *(const float4*)(b + lane * 4);
    float o0 = g4.x * (v[0] - mean) * inv + b4.x;
    float o1 = g4.y * (v[1] - mean) * inv + b4.y;
    float o2 = g4.z * (v[2] - mean) * inv + b4.z;
    float o3 = g4.w * (v[3] - mean) * inv + b4.w;
    *(float4*)(out + (size_t)w * 128 + lane * 4) = make_float4(o0, o1, o2, o3);
    uint32_t h0, l0, h1, l1;
    bf16_split2(o0, o1, h0, l0);
    bf16_split2(o2, o3, h1, l1);
    *(uint2*)(oH + (size_t)w * 64 + lane * 2) = make_uint2(h0, h1);
    *(uint2*)(oL + (size_t)w * 64 + lane * 2) = make_uint2(l0, l1);
}

// ---------------- GRU + LN3 (writes h fp32+planes, x fp32+planes) ----------------
__global__ void gru_ln_kernel(const float* __restrict__ hprev,
                              const float* __restrict__ lng, const float* __restrict__ lnb,
                              float* __restrict__ xout) {
    int w = (blockIdx.x * blockDim.x + threadIdx.x) >> 5;
    int lane = threadIdx.x & 31;
    if (w >= NN) return;
    size_t b3 = (size_t)w * 384;
    float hn[4], s = 0.f;
#pragma unroll
    for (int j = 0; j < 4; j++) {
        int e = lane * 4 + j;
        float ir = g_gi[b3 + e], iz = g_gi[b3 + 128 + e], in_ = g_gi[b3 + 256 + e];
        float hr = g_gh[b3 + e], hz = g_gh[b3 + 128 + e], hnn = g_gh[b3 + 256 + e];
        float hv = hprev[(size_t)w * 128 + e];
        float r = 1.f / (1.f + expf(-(ir + hr)));
        float z = 1.f / (1.f + expf(-(iz + hz)));
        float n = tanhf(in_ + r * hnn);
        float hnew = (1.f - z) * n + z * hv;
        hn[j] = hnew;
        s += hnew;
    }
    *(float4*)(g_h + (size_t)w * 128 + lane * 4) = make_float4(hn[0], hn[1], hn[2], hn[3]);
    {
        uint32_t h0, l0, h1, l1;
        bf16_split2(hn[0], hn[1], h0, l0);
        bf16_split2(hn[2], hn[3], h1, l1);
        *(uint2*)(g_hH + (size_t)w * 64 + lane * 2) = make_uint2(h0, h1);
        *(uint2*)(g_hL + (size_t)w * 64 + lane * 2) = make_uint2(l0, l1);
    }
#pragma unroll
    for (int off = 16; off > 0; off >>= 1) s += __shfl_xor_sync(0xffffffffu, s, off);
    float mean = s * (1.f / 128.f), s2 = 0.f;
#pragma unroll
    for (int j = 0; j < 4; j++) { float d = hn[j] - mean; s2 += d * d; }
#pragma unroll
    for (int off = 16; off > 0; off >>= 1) s2 += __shfl_xor_sync(0xffffffffu, s2, off);
    float inv = rsqrtf(s2 * (1.f / 128.f) + 1e-12f);
    float4 g4 = *(const float4*)(lng + lane * 4);
    float4 b4 = *(const float4*)(lnb + lane * 4);
    float o0 = g4.x * (hn[0] - mean) * inv + b4.x;
    float o1 = g4.y * (hn[1] - mean) * inv + b4.y;
    float o2 = g4.z * (hn[2] - mean) * inv + b4.z;
    float o3 = g4.w * (hn[3] - mean) * inv + b4.w;
    *(float4*)(xout + (size_t)w * 128 + lane * 4) = make_float4(o0, o1, o2, o3);
    uint32_t h0, l0, h1, l1;
    bf16_split2(o0, o1, h0, l0);
    bf16_split2(o2, o3, h1, l1);
    *(uint2*)(g_xH + (size_t)w * 64 + lane * 2) = make_uint2(h0, h1);
    *(uint2*)(g_xL + (size_t)w * 64 + lane * 2) = make_uint2(l0, l1);
}

// ---------------- host ----------------
static void* sym_addr(const void* symbol) {
    void* p = nullptr;
    cudaGetSymbolAddress(&p, symbol);
    return p;
}

extern "C" void kernel_launch(void* const* d_in, const int* in_sizes, int n_in,
                              void* d_out, int out_size) {
    (void)in_sizes; (void)n_in; (void)out_size;
    const float* x     = (const float*)d_in[0];
    const int*   ei    = (const int*)d_in[1];
    const float* eattr = (const float*)d_in[2];
    const float* wq  = (const float*)d_in[3];  const float* bq  = (const float*)d_in[4];
    const float* wk  = (const float*)d_in[5];  const float* bk  = (const float*)d_in[6];
    const float* wv  = (const float*)d_in[7];  const float* bv  = (const float*)d_in[8];
    const float* wao = (const float*)d_in[9];  const float* bao = (const float*)d_in[10];
    const float* ln1g = (const float*)d_in[11]; const float* ln1b = (const float*)d_in[12];
    const float* wint = (const float*)d_in[13]; const float* bint = (const float*)d_in[14];
    const float* wout = (const float*)d_in[15]; const float* bout = (const float*)d_in[16];
    const float* ln2g = (const float*)d_in[17]; const float* ln2b = (const float*)d_in[18];
    const float* wih = (const float*)d_in[19];  const float* whh = (const float*)d_in[20];
    const float* bih = (const float*)d_in[21];  const float* bhh = (const float*)d_in[22];
    const float* ln3g = (const float*)d_in[23]; const float* ln3b = (const float*)d_in[24];
    float* out = (float*)d_out;

    float* pP    = (float*)sym_addr(g_P);
    float* pSxe  = (float*)sym_addr(g_sxe);
    float* pPre  = (float*)sym_addr(g_pre);
    float* pAtt  = (float*)sym_addr(g_att);
    float* pInt  = (float*)sym_addr(g_inter);
    float* pM    = (float*)sym_addr(g_m);
    float* pH    = (float*)sym_addr(g_h);
    float* pX    = (float*)sym_addr(g_x);
    float* pGi   = (float*)sym_addr(g_gi);
    float* pGh   = (float*)sym_addr(g_gh);
    float* pBproj = (float*)sym_addr(g_bproj);
    float* pBav   = (float*)sym_addr(g_bav);
    float* pWbv   = (float*)sym_addr(g_wbv);
    uint32_t* pImg = (uint32_t*)sym_addr(g_img);
    uint32_t* pXH = (uint32_t*)sym_addr(g_xH);   uint32_t* pXL = (uint32_t*)sym_addr(g_xL);
    uint32_t* pHH = (uint32_t*)sym_addr(g_hH);   uint32_t* pHL = (uint32_t*)sym_addr(g_hL);
    uint32_t* pAH = (uint32_t*)sym_addr(g_attH); uint32_t* pAL = (uint32_t*)sym_addr(g_attL);
    uint32_t* pMH = (uint32_t*)sym_addr(g_mH);   uint32_t* pML = (uint32_t*)sym_addr(g_mL);
    uint32_t* pIH = (uint32_t*)sym_addr(g_intH); uint32_t* pIL = (uint32_t*)sym_addr(g_intL);

    const int* srcp = ei;
    const int* dstp = ei + EE;

    const int SMB = 18432 * 4;
    cudaFuncSetAttribute(gemm_bf16<1, 1, 0>, cudaFuncAttributeMaxDynamicSharedMemorySize, SMB);
    cudaFuncSetAttribute(gemm_bf16<2, 0, 0>, cudaFuncAttributeMaxDynamicSharedMemorySize, SMB);
    cudaFuncSetAttribute(gemm_bf16<3, 1, 1>, cudaFuncAttributeMaxDynamicSharedMemorySize, SMB);
    cudaFuncSetAttribute(gemm_bf16<2, 1, 0>, cudaFuncAttributeMaxDynamicSharedMemorySize, SMB);
    cudaFuncSetAttribute(scan_kernel, cudaFuncAttributeMaxDynamicSharedMemorySize, 40960 * 4);

    const int MT = (NN + 127) / 128;   // 313
    const int RG = (NN + 7) / 8;

    // launches 1-3 prep; launch 4 = proj GEMM (ncu capture slot)
    build_all<<<(204736 + 255) / 256, 256>>>(wq, wk, wv, wao, bq, bk, bv, bao);
    prep_w_all<<<(393216 + 255) / 256, 256>>>(wint, wout, wih, whh);
    split_x_kernel<<<(NN * 64 + 255) / 256, 256>>>(x);
    gemm_bf16<1, 1, 0><<<dim3(MT, 6), 256, SMB>>>(nullptr, pXH, pXL, 128,
        pImg + (size_t)IMG_PROJ * 9216, pBproj, nullptr, pP, nullptr, nullptr, NN, 2, 768);
    hist_kernel<<<(EE + 255) / 256, 256>>>(dstp);
    scan_kernel<<<1, 1024, 40960 * 4>>>();
    scatter_kernel<<<(EE + 255) / 256, 256>>>(srcp, dstp);

    for (int t = 0; t < 3; t++) {
        const float* xcur = (t == 0) ? x : pX;
        const float* hcur = (t == 0) ? x : pH;
        uint32_t* hHc = (t == 0) ? pXH : pHH;
        uint32_t* hLc = (t == 0) ? pXL : pHL;
        if (t > 0)
            gemm_bf16<1, 1, 0><<<dim3(MT, 6), 256, SMB>>>(nullptr, pXH, pXL, 128,
                pImg + (size_t)IMG_PROJ * 9216, pBproj, nullptr, pP, nullptr, nullptr, NN, 2, 768);
        gat2_kernel<<<RG, 256>>>(eattr, xcur);
        gemm_bf16<2, 0, 0><<<dim3(MT, 1), 256, SMB>>>(pSxe, nullptr, nullptr, 512,
            pImg + (size_t)IMG_WAV4 * 9216, pBav, xcur, pPre, nullptr, nullptr, NN, 8, 128);
        ln_kernel<<<RG, 256>>>(pPre, ln1g, ln1b, pWbv, pAtt, pAH, pAL);
        gemm_bf16<3, 1, 1><<<dim3(MT, 4), 256, SMB>>>(nullptr, pAH, pAL, 128,
            pImg + (size_t)IMG_WINT * 9216, bint, nullptr, pInt, pIH, pIL, NN, 2, 512);
        gemm_bf16<2, 1, 0><<<dim3(MT, 1), 256, SMB>>>(nullptr, pIH, pIL, 512,
            pImg + (size_t)IMG_WOUT * 9216, bout, pAtt, pPre, nullptr, nullptr, NN, 8, 128);
        ln_kernel<<<RG, 256>>>(pPre, ln2g, ln2b, nullptr, pM, pMH, pML);
        gemm_bf16<1, 1, 0><<<dim3(MT, 3), 256, SMB>>>(nullptr, pMH, pML, 128,
            pImg + (size_t)IMG_WIH * 9216, bih, nullptr, pGi, nullptr, nullptr, NN, 2, 384);
        gemm_bf16<1, 1, 0><<<dim3(MT, 3), 256, SMB>>>(nullptr, hHc, hLc, 128,
            pImg + (size_t)IMG_WHH * 9216, bhh, nullptr, pGh, nullptr, nullptr, NN, 2, 384);
        gru_ln_kernel<<<RG, 256>>>(hcur, ln3g, ln3b, (t == 2) ? out : pX);
    }
}

// round 8
// speedup vs baseline: 1.4830x; 1.0045x over previous
#include <cuda_runtime.h>
#include <cuda_bf16.h>
#include <cuda_fp16.h>
#include <math.h>
#include <stdint.h>

#define NN 40000
#define EE 320000

// ---------------- device scratch ----------------
__device__ __half g_Ph[(size_t)NN * 768];      // fp16 [q|k|qe]
__device__ __half g_sxeh[(size_t)NN * 512];    // fp16 GAT output
__device__ __half g_eh[(size_t)EE * 128];      // fp16 edge_attr
__device__ __half g_xh[NN * 128];              // fp16 x mirror
__device__ float g_pre[NN * 128];
__device__ float g_att[NN * 128];
__device__ uint32_t g_attH[NN * 64], g_attL[NN * 64];
__device__ uint32_t g_intH[(size_t)NN * 256], g_intL[(size_t)NN * 256];
__device__ uint32_t g_mhH[(size_t)NN * 128], g_mhL[(size_t)NN * 128];  // [m|h] planes
__device__ float g_grz[(size_t)NN * 256];
__device__ float g_gn[(size_t)NN * 256];       // [gn_i | gn_h]
__device__ float g_h[NN * 128];
__device__ float g_x[NN * 128];
__device__ float g_WprojF[768 * 128];
__device__ float g_Wav4F[128 * 512];
__device__ float g_Wgrz[256 * 256];
__device__ float g_bproj[768], g_bav[128], g_wbv[128], g_brz[256], g_bn[256];
__device__ uint32_t g_img[(size_t)48 * 9216];
__device__ int g_cnt[NN], g_rowptr[NN + 1], g_cur[NN], g_srcs[EE], g_eidxs[EE];

#define IMG_PROJ 0
#define IMG_WAV4 12
#define IMG_WINT 20
#define IMG_WOUT 28
#define IMG_GRZ  36
#define IMG_GN   44

// ---------------- helpers ----------------
__device__ __forceinline__ void bf16_split2(float a, float b, uint32_t& hi, uint32_t& lo) {
    __nv_bfloat16 ha = __float2bfloat16(a), hb = __float2bfloat16(b);
    float ra = a - __bfloat162float(ha), rb = b - __bfloat162float(hb);
    __nv_bfloat16 la = __float2bfloat16(ra), lb = __float2bfloat16(rb);
    hi = (uint32_t)__bfloat16_as_ushort(ha) | ((uint32_t)__bfloat16_as_ushort(hb) << 16);
    lo = (uint32_t)__bfloat16_as_ushort(la) | ((uint32_t)__bfloat16_as_ushort(lb) << 16);
}
__device__ __forceinline__ void mma_bf16(float* d, const uint32_t* a, uint32_t b0, uint32_t b1) {
    asm volatile(
        "mma.sync.aligned.m16n8k16.row.col.f32.bf16.bf16.f32 "
        "{%0,%1,%2,%3}, {%4,%5,%6,%7}, {%8,%9}, {%0,%1,%2,%3};"
        : "+f"(d[0]), "+f"(d[1]), "+f"(d[2]), "+f"(d[3])
        : "r"(a[0]), "r"(a[1]), "r"(a[2]), "r"(a[3]), "r"(b0), "r"(b1));
}
__device__ __forceinline__ void ldm_x4(uint32_t* r, uint32_t addr) {
    asm volatile("ldmatrix.sync.aligned.m8n8.x4.shared.b16 {%0,%1,%2,%3}, [%4];"
                 : "=r"(r[0]), "=r"(r[1]), "=r"(r[2]), "=r"(r[3]) : "r"(addr));
}
__device__ __forceinline__ uint32_t smem_u32p(const void* p) {
    uint32_t a;
    asm("{ .reg .u64 t; cvta.to.shared.u64 t, %1; cvt.u32.u64 %0, t; }" : "=r"(a) : "l"(p));
    return a;
}
__device__ __forceinline__ void ld4h(const __half* p, float* f) {
    uint2 u = *(const uint2*)p;
    float2 fa = __half22float2(*(__half2*)&u.x);
    float2 fb = __half22float2(*(__half2*)&u.y);
    f[0] = fa.x; f[1] = fa.y; f[2] = fb.x; f[3] = fb.y;
}
__device__ __forceinline__ void st4h(__half* p, float a, float b, float c, float d) {
    __half2 h0 = __floats2half2_rn(a, b), h1 = __floats2half2_rn(c, d);
    uint2 u;
    u.x = *(uint32_t*)&h0; u.y = *(uint32_t*)&h1;
    *(uint2*)p = u;
}

// ---------------- fused prep #1 ----------------
__global__ void build_all(const float* __restrict__ wq, const float* __restrict__ wk,
                          const float* __restrict__ wv, const float* __restrict__ wao,
                          const float* __restrict__ bq, const float* __restrict__ bk,
                          const float* __restrict__ bv, const float* __restrict__ bao,
                          const float* __restrict__ wih, const float* __restrict__ whh,
                          const float* __restrict__ bih, const float* __restrict__ bhh) {
    int idx = blockIdx.x * blockDim.x + threadIdx.x;
    const float SC = 0.17677669529663687f;
    if (idx < 98304) {
        int n = idx >> 7, k = idx & 127;
        float v;
        if (n < 128) v = wq[n * 128 + k] * SC;
        else if (n < 256) v = wk[(n - 128) * 128 + k];
        else {
            int h = (n - 256) >> 7, d1 = (n - 256) & 127;
            float s = 0.f;
            for (int r = 0; r < 32; r++)
                s += wk[(h * 32 + r) * 128 + d1] * wq[(h * 32 + r) * 128 + k];
            v = s * SC;
        }
        g_WprojF[idx] = v;
    } else if (idx < 163840) {
        int i2 = idx - 98304;
        int n = i2 >> 9, m = i2 & 511;
        int h = m >> 7, d = m & 127;
        float s = 0.f;
        for (int r = 0; r < 32; r++)
            s += wao[n * 128 + h * 32 + r] * wv[(h * 32 + r) * 128 + d];
        g_Wav4F[i2] = s;
    } else if (idx < 164608) {
        int n = idx - 163840;
        float v;
        if (n < 128) v = bq[n] * SC;
        else if (n < 256) v = bk[n - 128];
        else {
            int h = (n - 256) >> 7, d1 = (n - 256) & 127;
            float s = 0.f;
            for (int r = 0; r < 32; r++)
                s += wk[(h * 32 + r) * 128 + d1] * bq[h * 32 + r];
            v = s * SC;
        }
        g_bproj[n] = v;
    } else if (idx < 164736) {
        int n = idx - 164608;
        float s = 0.f;
        for (int k = 0; k < 128; k++) s += wao[n * 128 + k] * bv[k];
        g_wbv[n] = s;
        g_bav[n] = s + bao[n];
    } else if (idx < 230272) {            // Wgrz [256 x 256] = [Wih_rz | Whh_rz]
        int i = idx - 164736;
        int n = i >> 8, k = i & 255;
        g_Wgrz[i] = (k < 128) ? wih[n * 128 + k] : whh[n * 128 + (k - 128)];
    } else if (idx < 230528) {
        int n = idx - 230272;
        g_brz[n] = bih[n] + bhh[n];
    } else if (idx < 230784) {
        int n = idx - 230528;
        g_bn[n] = (n < 128) ? bih[256 + n] : bhh[256 + (n - 128)];
    } else if (idx < 270784) {
        g_cnt[idx - 230784] = 0;
    }
}

// ---------------- fused prep #2: weights -> bf16 hi/lo chunk-images ----------------
__device__ __forceinline__ void img_write(const float* src, int i2, int K, int base) {
    int n = i2 / K, k = i2 % K;
    float v = src[i2];
    __nv_bfloat16 h = __float2bfloat16(v);
    __nv_bfloat16 l = __float2bfloat16(v - __bfloat162float(h));
    int KC = K >> 6;
    size_t im = (size_t)(base + (n >> 7) * KC + (k >> 6));
    size_t word = im * 9216 + (n & 127) * 36 + ((k & 63) >> 1);
    unsigned short* p = (unsigned short*)g_img;
    p[word * 2 + (k & 1)] = __bfloat16_as_ushort(h);
    p[(word + 4608) * 2 + (k & 1)] = __bfloat16_as_ushort(l);
}
__global__ void prep_w_all(const float* __restrict__ wint, const float* __restrict__ wout,
                           const float* __restrict__ wih, const float* __restrict__ whh) {
    int idx = blockIdx.x * blockDim.x + threadIdx.x;
    if (idx < 98304)       img_write(g_WprojF, idx, 128, IMG_PROJ);
    else if (idx < 163840) img_write(g_Wav4F, idx - 98304, 512, IMG_WAV4);
    else if (idx < 229376) img_write(wint, idx - 163840, 128, IMG_WINT);
    else if (idx < 294912) img_write(wout, idx - 229376, 512, IMG_WOUT);
    else if (idx < 360448) img_write(g_Wgrz, idx - 294912, 256, IMG_GRZ);
    else if (idx < 376832) img_write(wih + 256 * 128, idx - 360448, 128, IMG_GN);
    else if (idx < 393216) img_write(whh + 256 * 128, idx - 376832, 128, IMG_GN + 2);
}

// convert x -> fp16 + mh h-planes; eattr -> fp16
__global__ void split_conv(const float* __restrict__ x, const float* __restrict__ eattr) {
    int idx = blockIdx.x * blockDim.x + threadIdx.x;
    if (idx < NN * 64) {
        float2 f = *(const float2*)(x + 2 * idx);
        *(__half2*)(g_xh + 2 * idx) = __floats2half2_rn(f.x, f.y);
        uint32_t hi, lo;
        bf16_split2(f.x, f.y, hi, lo);
        int w = idx >> 6, jw = idx & 63;
        g_mhH[(size_t)w * 128 + 64 + jw] = hi;
        g_mhL[(size_t)w * 128 + 64 + jw] = lo;
    } else if (idx < NN * 64 + EE * 64) {
        size_t i2 = idx - NN * 64;
        float2 f = *(const float2*)(eattr + 2 * i2);
        *(__half2*)(g_eh + 2 * i2) = __floats2half2_rn(f.x, f.y);
    }
}

// ---------------- CSR build ----------------
__global__ void hist_kernel(const int* __restrict__ dst) {
    int i = blockIdx.x * blockDim.x + threadIdx.x;
    if (i < EE) atomicAdd(&g_cnt[dst[i]], 1);
}
__global__ void scan_kernel() {
    extern __shared__ int sbuf[];
    __shared__ int wsum[32];
    int t = threadIdx.x;
    for (int i = 0; i < 40; i++) {
        int j = i * 1024 + t;
        sbuf[j] = (j < NN) ? g_cnt[j] : 0;
    }
    __syncthreads();
    int s = 0;
    for (int i = 0; i < 40; i++) s += sbuf[t * 40 + i];
    int lane = t & 31, wid = t >> 5;
    int v = s;
#pragma unroll
    for (int off = 1; off < 32; off <<= 1) {
        int n = __shfl_up_sync(0xffffffffu, v, off);
        if (lane >= off) v += n;
    }
    if (lane == 31) wsum[wid] = v;
    __syncthreads();
    if (wid == 0) {
        int w = wsum[lane];
#pragma unroll
        for (int off = 1; off < 32; off <<= 1) {
            int n = __shfl_up_sync(0xffffffffu, w, off);
            if (lane >= off) w += n;
        }
        wsum[lane] = w;
    }
    __syncthreads();
    int r = v - s + (wid > 0 ? wsum[wid - 1] : 0);
    for (int i = 0; i < 40; i++) {
        int tmp = sbuf[t * 40 + i];
        sbuf[t * 40 + i] = r;
        r += tmp;
    }
    __syncthreads();
    for (int i = 0; i < 40; i++) {
        int j = i * 1024 + t;
        if (j < NN) { g_rowptr[j] = sbuf[j]; g_cur[j] = sbuf[j]; }
    }
    if (t == 1023) g_rowptr[NN] = wsum[31];
}
__global__ void scatter_kernel(const int* __restrict__ src, const int* __restrict__ dst) {
    int i = blockIdx.x * blockDim.x + threadIdx.x;
    if (i >= EE) return;
    int d = dst[i];
    int p = atomicAdd(&g_cur[d], 1);
    g_srcs[p] = src[i];
    g_eidxs[p] = i;
}

// ---------------- bf16 3-term mma GEMM ----------------
// AFMT: 1 = bf16 hi/lo planes (Aa=AH + AL), 2 = fp16
// OFMT: 0 = fp32, 2 = fp16, 3 = planes only
// EPI: 1 bias, 2 bias+residual(fp32), 3 bias+gelu
template <int EPI, int AFMT, int OFMT>
__global__ void __launch_bounds__(256, 2) gemm_bf16(
    const void* __restrict__ Aa, int rsw, int aoffy,
    const uint32_t* __restrict__ AL,
    const uint32_t* __restrict__ img,
    const float* __restrict__ bias, const float* __restrict__ res,
    void* __restrict__ outp, uint32_t* __restrict__ oH, uint32_t* __restrict__ oL, int opst,
    int M, int KC, int ldo)
{
    extern __shared__ uint32_t smw[];
    uint32_t* AhS = smw;
    uint32_t* AlS = smw + 4608;
    uint32_t* BS  = smw + 9216;

    const int tid = threadIdx.x;
    const int warp = tid >> 5, lane = tid & 31;
    const int wm = warp >> 1, wn = warp & 1;
    const int lr = lane >> 2, lk = lane & 3;
    const int bm = blockIdx.x * 128;
    const int yoff = blockIdx.y * aoffy;

    float acc[2][8][4];
#pragma unroll
    for (int i = 0; i < 2; i++)
#pragma unroll
        for (int j = 0; j < 8; j++)
#pragma unroll
            for (int l = 0; l < 4; l++) acc[i][j][l] = 0.f;

    const uint32_t smb = smem_u32p(smw);
    const int a_row = ((lane >> 3) & 1) * 8 + (lane & 7);
    const int a_wrd = (lane >> 4) * 4;
    const uint32_t aAddr = smb + (uint32_t)(((wm * 32 + a_row) * 36 + a_wrd) * 4);
    const int b_row = ((lane >> 4) & 1) * 8 + (lane & 7);
    const int b_wrd = ((lane >> 3) & 1) * 4;
    const uint32_t bAddr = smb + 9216u * 4 + (uint32_t)(((wn * 64 + b_row) * 36 + b_wrd) * 4);

    int gr = bm + (tid >> 1);
    if (gr >= M) gr = M - 1;
    const int half = tid & 1;
    uint32_t* dh = AhS + (tid >> 1) * 36 + half * 16;
    uint32_t* dl = AlS + (tid >> 1) * 36 + half * 16;
    const uint32_t* ahsrc = (AFMT == 1) ? ((const uint32_t*)Aa + (size_t)gr * rsw + yoff + half * 16) : nullptr;
    const uint32_t* alsrc = (AFMT == 1) ? (AL + (size_t)gr * rsw + yoff + half * 16) : nullptr;
    const __half* ahalf = (AFMT == 2) ? ((const __half*)Aa + (size_t)gr * rsw + yoff + half * 32) : nullptr;
    const uint4* bimg = (const uint4*)(img + (size_t)blockIdx.y * KC * 9216);

    for (int c = 0; c < KC; c++) {
        if (AFMT == 1) {
            const uint4* sh4 = (const uint4*)(ahsrc + c * 32);
            const uint4* sl4 = (const uint4*)(alsrc + c * 32);
#pragma unroll
            for (int p = 0; p < 4; p++) {
                *(uint4*)(dh + p * 4) = sh4[p];
                *(uint4*)(dl + p * 4) = sl4[p];
            }
        } else {
            const __half* s0 = ahalf + c * 64;
#pragma unroll
            for (int p = 0; p < 8; p++) {
                float f[4];
                ld4h(s0 + p * 4, f);
                bf16_split2(f[0], f[1], dh[2 * p], dl[2 * p]);
                bf16_split2(f[2], f[3], dh[2 * p + 1], dl[2 * p + 1]);
            }
        }
        {
            const uint4* bsrc4 = bimg + (size_t)c * 2304;
#pragma unroll
            for (int j = 0; j < 9; j++)
                *(uint4*)(BS + (j * 256 + tid) * 4) = bsrc4[j * 256 + tid];
        }
        __syncthreads();

#pragma unroll
        for (int s = 0; s < 4; s++) {
            uint32_t ah[2][4], al[2][4];
            ldm_x4(ah[0], aAddr + (0 * 576 + s * 8) * 4);
            ldm_x4(ah[1], aAddr + (1 * 576 + s * 8) * 4);
            ldm_x4(al[0], aAddr + 4608u * 4 + (0 * 576 + s * 8) * 4);
            ldm_x4(al[1], aAddr + 4608u * 4 + (1 * 576 + s * 8) * 4);
#pragma unroll
            for (int ntp = 0; ntp < 4; ntp++) {
                uint32_t bh[4], bl[4];
                ldm_x4(bh, bAddr + (ntp * 576 + s * 8) * 4);
                ldm_x4(bl, bAddr + 4608u * 4 + (ntp * 576 + s * 8) * 4);
#pragma unroll
                for (int hf = 0; hf < 2; hf++) {
                    int nt = ntp * 2 + hf;
#pragma unroll
                    for (int mt = 0; mt < 2; mt++) {
                        mma_bf16(acc[mt][nt], ah[mt], bh[2 * hf], bh[2 * hf + 1]);
                        mma_bf16(acc[mt][nt], ah[mt], bl[2 * hf], bl[2 * hf + 1]);
                        mma_bf16(acc[mt][nt], al[mt], bh[2 * hf], bh[2 * hf + 1]);
                    }
                }
            }
        }
        __syncthreads();
    }

    const int cbase = blockIdx.y * 128 + wn * 64;
#pragma unroll
    for (int mt = 0; mt < 2; mt++) {
        int r0 = bm + wm * 32 + mt * 16 + lr;
#pragma unroll
        for (int hf = 0; hf < 2; hf++) {
            int row = r0 + hf * 8;
            if (row >= M) continue;
            const float* rrow = (EPI == 2) ? (res + (size_t)row * ldo + cbase) : nullptr;
#pragma unroll
            for (int nt = 0; nt < 8; nt++) {
                int cl = nt * 8 + lk * 2;
                float v0 = acc[mt][nt][hf * 2 + 0];
                float v1 = acc[mt][nt][hf * 2 + 1];
                v0 += bias[cbase + cl];
                v1 += bias[cbase + cl + 1];
                if (EPI == 2) { v0 += rrow[cl]; v1 += rrow[cl + 1]; }
                if (EPI == 3) {
                    v0 = 0.5f * v0 * (1.f + erff(v0 * 0.70710678118654752f));
                    v1 = 0.5f * v1 * (1.f + erff(v1 * 0.70710678118654752f));
                }
                if (OFMT == 0) {
                    *(float2*)((float*)outp + (size_t)row * ldo + cbase + cl) = make_float2(v0, v1);
                } else if (OFMT == 2) {
                    *(__half2*)((__half*)outp + (size_t)row * ldo + cbase + cl) = __floats2half2_rn(v0, v1);
                } else {
                    uint32_t hi, lo;
                    bf16_split2(v0, v1, hi, lo);
                    size_t pw = (size_t)row * opst + ((cbase + cl) >> 1);
                    oH[pw] = hi;
                    oL[pw] = lo;
                }
            }
        }
    }
}

// ---------------- GAT: warp per node, fp16 operands ----------------
__global__ void gat2_kernel() {
    int w = (blockIdx.x * blockDim.x + threadIdx.x) >> 5;
    int lane = threadIdx.x & 31;
    if (w >= NN) return;
    const __half* pw = g_Ph + (size_t)w * 768;
    float q[4], qe[4][4], mx[4], smx[4], acc[4][4];
    ld4h(pw + lane * 4, q);
#pragma unroll
    for (int h = 0; h < 4; h++) {
        ld4h(pw + 256 + h * 128 + lane * 4, qe[h]);
#pragma unroll
        for (int j = 0; j < 4; j++) acc[h][j] = 0.f;
        mx[h] = -1e30f; smx[h] = 0.f;
    }
    const int myhead = lane >> 3;
    int beg = g_rowptr[w], end = g_rowptr[w + 1];
    for (int p = beg; p < end; p++) {
        int s = g_srcs[p], ei = g_eidxs[p];
        float kv[4], ev[4], xv[4], u[4];
        ld4h(g_Ph + (size_t)s * 768 + 128 + lane * 4, kv);
        ld4h(g_eh + (size_t)ei * 128 + lane * 4, ev);
        ld4h(g_xh + (size_t)s * 128 + lane * 4, xv);
        float qk = 0.f;
#pragma unroll
        for (int j = 0; j < 4; j++) {
            u[j] = xv[j] + ev[j];
            qk += q[j] * kv[j];
        }
        float d[4];
#pragma unroll
        for (int h = 0; h < 4; h++)
            d[h] = qe[h][0] * ev[0] + qe[h][1] * ev[1] + qe[h][2] * ev[2] + qe[h][3] * ev[3];
        d[myhead] += qk;
#pragma unroll
        for (int off = 16; off > 0; off >>= 1)
#pragma unroll
            for (int h = 0; h < 4; h++)
                d[h] += __shfl_xor_sync(0xffffffffu, d[h], off);
#pragma unroll
        for (int h = 0; h < 4; h++) {
            float a = d[h];
            float nm = fmaxf(mx[h], a);
            float csc = __expf(mx[h] - nm);
            float pe = __expf(a - nm);
            smx[h] = smx[h] * csc + pe;
#pragma unroll
            for (int j = 0; j < 4; j++)
                acc[h][j] = acc[h][j] * csc + pe * u[j];
            mx[h] = nm;
        }
    }
    __half* o = g_sxeh + (size_t)w * 512;
#pragma unroll
    for (int h = 0; h < 4; h++) {
        float inv = 1.f / (smx[h] + 1e-16f);
        st4h(o + h * 128 + lane * 4, acc[h][0] * inv, acc[h][1] * inv,
             acc[h][2] * inv, acc[h][3] * inv);
    }
}

// ---------------- LayerNorm: fp32 in; optional fp32 out; plane out ----------------
__global__ void ln_kernel(const float* __restrict__ in, const float* __restrict__ g,
                          const float* __restrict__ b, const float* __restrict__ corr,
                          float* __restrict__ outF, uint32_t* __restrict__ oH,
                          uint32_t* __restrict__ oL, int pst, int poff) {
    int w = (blockIdx.x * blockDim.x + threadIdx.x) >> 5;
    int lane = threadIdx.x & 31;
    if (w >= NN) return;
    const float* row = in + (size_t)w * 128;
    float4 v4 = *(const float4*)(row + lane * 4);
    float v[4] = {v4.x, v4.y, v4.z, v4.w};
    if (corr && g_rowptr[w] == g_rowptr[w + 1]) {
        float4 c4 = *(const float4*)(corr + lane * 4);
        v[0] -= c4.x; v[1] -= c4.y; v[2] -= c4.z; v[3] -= c4.w;
    }
    float s = v[0] + v[1] + v[2] + v[3];
#pragma unroll
    for (int off = 16; off > 0; off >>= 1) s += __shfl_xor_sync(0xffffffffu, s, off);
    float mean = s * (1.f / 128.f), s2 = 0.f;
#pragma unroll
    for (int j = 0; j < 4; j++) { float d = v[j] - mean; s2 += d * d; }
#pragma unroll
    for (int off = 16; off > 0; off >>= 1) s2 += __shfl_xor_sync(0xffffffffu, s2, off);
    float inv = rsqrtf(s2 * (1.f / 128.f) + 1e-12f);
    float4 g4 = *(const float4*)(g + lane * 4);
    float4 b4 = *(const float4*)(b + lane * 4);
    float o0 = g4.x * (v[0] - mean) * inv + b4.x;
    float o1 = g4.y * (v[1] - mean) * inv + b4.y;
    float o2 = g4.z * (v[2] - mean) * inv + b4.z;
    float o3 = g4.w * (v[3] - mean) * inv + b4.w;
    if (outF)
        *(float4*)(outF + (size_t)w * 128 + lane * 4) = make_float4(o0, o1, o2, o3);
    uint32_t h0, l0, h1, l1;
    bf16_split2(o0, o1, h0, l0);
    bf16_split2(o2, o3, h1, l1);
    size_t pw = (size_t)w * pst + poff + lane * 2;
    oH[pw] = h0; oH[pw + 1] = h1;
    oL[pw] = l0; oL[pw + 1] = l1;
}

// ---------------- GRU + LN3 ----------------
__global__ void gru_ln_kernel(const float* __restrict__ hprev,
                              const float* __restrict__ lng, const float* __restrict__ lnb,
                              float* __restrict__ xout) {
    int w = (blockIdx.x * blockDim.x + threadIdx.x) >> 5;
    int lane = threadIdx.x & 31;
    if (w >= NN) return;
    float4 r4 = *(const float4*)(g_grz + (size_t)w * 256 + lane * 4);
    float4 z4 = *(const float4*)(g_grz + (size_t)w * 256 + 128 + lane * 4);
    float4 ni4 = *(const float4*)(g_gn + (size_t)w * 256 + lane * 4);
    float4 nh4 = *(const float4*)(g_gn + (size_t)w * 256 + 128 + lane * 4);
    float4 h4 = *(const float4*)(hprev + (size_t)w * 128 + lane * 4);
    float rr[4] = {r4.x, r4.y, r4.z, r4.w};
    float zz[4] = {z4.x, z4.y, z4.z, z4.w};
    float ni[4] = {ni4.x, ni4.y, ni4.z, ni4.w};
    float nh[4] = {nh4.x, nh4.y, nh4.z, nh4.w};
    float hv[4] = {h4.x, h4.y, h4.z, h4.w};
    float hn[4], s = 0.f;
#pragma unroll
    for (int j = 0; j < 4; j++) {
        float r = 1.f / (1.f + expf(-rr[j]));
        float z = 1.f / (1.f + expf(-zz[j]));
        float n = tanhf(ni[j] + r * nh[j]);
        hn[j] = (1.f - z) * n + z * hv[j];
        s += hn[j];
    }
    *(float4*)(g_h + (size_t)w * 128 + lane * 4) = make_float4(hn[0], hn[1], hn[2], hn[3]);
    {
        uint32_t h0, l0, h1, l1;
        bf16_split2(hn[0], hn[1], h0, l0);
        bf16_split2(hn[2], hn[3], h1, l1);
        size_t pw = (size_t)w * 128 + 64 + lane * 2;
        g_mhH[pw] = h0; g_mhH[pw + 1] = h1;
        g_mhL[pw] = l0; g_mhL[pw + 1] = l1;
    }
#pragma unroll
    for (int off = 16; off > 0; off >>= 1) s += __shfl_xor_sync(0xffffffffu, s, off);
    float mean = s * (1.f / 128.f), s2 = 0.f;
#pragma unroll
    for (int j = 0; j < 4; j++) { float d = hn[j] - mean; s2 += d * d; }
#pragma unroll
    for (int off = 16; off > 0; off >>= 1) s2 += __shfl_xor_sync(0xffffffffu, s2, off);
    float inv = rsqrtf(s2 * (1.f / 128.f) + 1e-12f);
    float4 g4 = *(const float4*)(lng + lane * 4);
    float4 b4 = *(const float4*)(lnb + lane * 4);
    float o0 = g4.x * (hn[0] - mean) * inv + b4.x;
    float o1 = g4.y * (hn[1] - mean) * inv + b4.y;
    float o2 = g4.z * (hn[2] - mean) * inv + b4.z;
    float o3 = g4.w * (hn[3] - mean) * inv + b4.w;
    *(float4*)(xout + (size_t)w * 128 + lane * 4) = make_float4(o0, o1, o2, o3);
    st4h(g_xh + (size_t)w * 128 + lane * 4, o0, o1, o2, o3);
}

// ---------------- host ----------------
static void* sym_addr(const void* symbol) {
    void* p = nullptr;
    cudaGetSymbolAddress(&p, symbol);
    return p;
}

extern "C" void kernel_launch(void* const* d_in, const int* in_sizes, int n_in,
                              void* d_out, int out_size) {
    (void)in_sizes; (void)n_in; (void)out_size;
    const float* x     = (const float*)d_in[0];
    const int*   ei    = (const int*)d_in[1];
    const float* eattr = (const float*)d_in[2];
    const float* wq  = (const float*)d_in[3];  const float* bq  = (const float*)d_in[4];
    const float* wk  = (const float*)d_in[5];  const float* bk  = (const float*)d_in[6];
    const float* wv  = (const float*)d_in[7];  const float* bv  = (const float*)d_in[8];
    const float* wao = (const float*)d_in[9];  const float* bao = (const float*)d_in[10];
    const float* ln1g = (const float*)d_in[11]; const float* ln1b = (const float*)d_in[12];
    const float* wint = (const float*)d_in[13]; const float* bint = (const float*)d_in[14];
    const float* wout = (const float*)d_in[15]; const float* bout = (const float*)d_in[16];
    const float* ln2g = (const float*)d_in[17]; const float* ln2b = (const float*)d_in[18];
    const float* wih = (const float*)d_in[19];  const float* whh = (const float*)d_in[20];
    const float* bih = (const float*)d_in[21];  const float* bhh = (const float*)d_in[22];
    const float* ln3g = (const float*)d_in[23]; const float* ln3b = (const float*)d_in[24];
    float* out = (float*)d_out;

    __half* pPh   = (__half*)sym_addr(g_Ph);
    __half* pSxeh = (__half*)sym_addr(g_sxeh);
    __half* pXh   = (__half*)sym_addr(g_xh);
    float* pPre  = (float*)sym_addr(g_pre);
    float* pAtt  = (float*)sym_addr(g_att);
    float* pGrz  = (float*)sym_addr(g_grz);
    float* pGn   = (float*)sym_addr(g_gn);
    float* pH    = (float*)sym_addr(g_h);
    float* pX    = (float*)sym_addr(g_x);
    float* pBproj = (float*)sym_addr(g_bproj);
    float* pBav   = (float*)sym_addr(g_bav);
    float* pWbv   = (float*)sym_addr(g_wbv);
    float* pBrz   = (float*)sym_addr(g_brz);
    float* pBn    = (float*)sym_addr(g_bn);
    uint32_t* pImg = (uint32_t*)sym_addr(g_img);
    uint32_t* pAH = (uint32_t*)sym_addr(g_attH); uint32_t* pAL = (uint32_t*)sym_addr(g_attL);
    uint32_t* pIH = (uint32_t*)sym_addr(g_intH); uint32_t* pIL = (uint32_t*)sym_addr(g_intL);
    uint32_t* pMH = (uint32_t*)sym_addr(g_mhH);  uint32_t* pML = (uint32_t*)sym_addr(g_mhL);

    const int* srcp = ei;
    const int* dstp = ei + EE;

    const int SMB = 18432 * 4;
    cudaFuncSetAttribute(gemm_bf16<1, 2, 2>, cudaFuncAttributeMaxDynamicSharedMemorySize, SMB);
    cudaFuncSetAttribute(gemm_bf16<2, 2, 0>, cudaFuncAttributeMaxDynamicSharedMemorySize, SMB);
    cudaFuncSetAttribute(gemm_bf16<3, 1, 3>, cudaFuncAttributeMaxDynamicSharedMemorySize, SMB);
    cudaFuncSetAttribute(gemm_bf16<2, 1, 0>, cudaFuncAttributeMaxDynamicSharedMemorySize, SMB);
    cudaFuncSetAttribute(gemm_bf16<1, 1, 0>, cudaFuncAttributeMaxDynamicSharedMemorySize, SMB);
    cudaFuncSetAttribute(scan_kernel, cudaFuncAttributeMaxDynamicSharedMemorySize, 40960 * 4);

    const int MT = (NN + 127) / 128;
    const int RG = (NN + 7) / 8;

    // launches 1-3 prep; launch 4 = proj GEMM (ncu slot)
    build_all<<<(270784 + 255) / 256, 256>>>(wq, wk, wv, wao, bq, bk, bv, bao, wih, whh, bih, bhh);
    prep_w_all<<<(393216 + 255) / 256, 256>>>(wint, wout, wih, whh);
    split_conv<<<(NN * 64 + EE * 64 + 255) / 256, 256>>>(x, eattr);
    gemm_bf16<1, 2, 2><<<dim3(MT, 6), 256, SMB>>>(pXh, 128, 0, nullptr,
        pImg + (size_t)IMG_PROJ * 9216, pBproj, nullptr, pPh, nullptr, nullptr, 0, NN, 2, 768);
    hist_kernel<<<(EE + 255) / 256, 256>>>(dstp);
    scan_kernel<<<1, 1024, 40960 * 4>>>();
    scatter_kernel<<<(EE + 255) / 256, 256>>>(srcp, dstp);

    for (int t = 0; t < 3; t++) {
        const float* xcur = (t == 0) ? x : pX;
        const float* hcur = (t == 0) ? x : pH;
        if (t > 0)
            gemm_bf16<1, 2, 2><<<dim3(MT, 6), 256, SMB>>>(pXh, 128, 0, nullptr,
                pImg + (size_t)IMG_PROJ * 9216, pBproj, nullptr, pPh, nullptr, nullptr, 0, NN, 2, 768);
        gat2_kernel<<<RG, 256>>>();
        gemm_bf16<2, 2, 0><<<dim3(MT, 1), 256, SMB>>>(pSxeh, 512, 0, nullptr,
            pImg + (size_t)IMG_WAV4 * 9216, pBav, xcur, pPre, nullptr, nullptr, 0, NN, 8, 128);
        ln_kernel<<<RG, 256>>>(pPre, ln1g, ln1b, pWbv, pAtt, pAH, pAL, 64, 0);
        gemm_bf16<3, 1, 3><<<dim3(MT, 4), 256, SMB>>>(pAH, 64, 0, pAL,
            pImg + (size_t)IMG_WINT * 9216, bint, nullptr, nullptr, pIH, pIL, 256, NN, 2, 512);
        gemm_bf16<2, 1, 0><<<dim3(MT, 1), 256, SMB>>>(pIH, 256, 0, pIL,
            pImg + (size_t)IMG_WOUT * 9216, bout, pAtt, pPre, nullptr, nullptr, 0, NN, 8, 128);
        ln_kernel<<<RG, 256>>>(pPre, ln2g, ln2b, nullptr, nullptr, pMH, pML, 128, 0);
        gemm_bf16<1, 1, 0><<<dim3(MT, 2), 256, SMB>>>(pMH, 128, 0, pML,
            pImg + (size_t)IMG_GRZ * 9216, pBrz, nullptr, pGrz, nullptr, nullptr, 0, NN, 4, 256);
        gemm_bf16<1, 1, 0><<<dim3(MT, 2), 256, SMB>>>(pMH, 128, 64, pML,
            pImg + (size_t)IMG_GN * 9216, pBn, nullptr, pGn, nullptr, nullptr, 0, NN, 2, 256);
        gru_ln_kernel<<<RG, 256>>>(hcur, ln3g, ln3b, (t == 2) ? out : pX);
    }
}

// round 9
// speedup vs baseline: 1.9318x; 1.3027x over previous
#include <cuda_runtime.h>
#include <cuda_fp16.h>
#include <math.h>
#include <stdint.h>

#define NN 40000
#define EE 320000

// ---------------- device scratch ----------------
__device__ __half g_Ph[(size_t)NN * 768];      // fp16 [q|k|qe]
__device__ __half g_sxeh[(size_t)NN * 512];    // fp16 GAT output
__device__ __half g_eh[(size_t)EE * 128];      // fp16 edge_attr
__device__ __half g_xh[NN * 128];              // fp16 x mirror
__device__ __half g_atth[NN * 128];            // fp16 att (LN1 out)
__device__ __half g_inth[(size_t)NN * 512];    // fp16 FFN mid
__device__ __half g_mhh[(size_t)NN * 256];     // fp16 [m|h]
__device__ float g_pre[NN * 128];
__device__ float g_att[NN * 128];
__device__ float g_grz[(size_t)NN * 256];
__device__ float g_gn[(size_t)NN * 256];
__device__ float g_h[NN * 128];
__device__ float g_x[NN * 128];
__device__ float g_WprojF[768 * 128];
__device__ float g_Wav4F[128 * 512];
__device__ float g_Wgrz[256 * 256];
__device__ float g_bproj[768], g_bav[128], g_wbv[128], g_brz[256], g_bn[256];
// fp16 hi/lo weight chunk-images: [hi 128x36 | lo 128x36] u32 = 9216 words each
__device__ uint32_t g_img[(size_t)48 * 9216];
__device__ int g_cnt[NN], g_rowptr[NN + 1], g_cur[NN], g_srcs[EE], g_eidxs[EE];

#define IMG_PROJ 0
#define IMG_WAV4 12
#define IMG_WINT 20
#define IMG_WOUT 28
#define IMG_GRZ  36
#define IMG_GN   44

// ---------------- helpers ----------------
__device__ __forceinline__ void mma_f16(float* d, const uint32_t* a, uint32_t b0, uint32_t b1) {
    asm volatile(
        "mma.sync.aligned.m16n8k16.row.col.f32.f16.f16.f32 "
        "{%0,%1,%2,%3}, {%4,%5,%6,%7}, {%8,%9}, {%0,%1,%2,%3};"
        : "+f"(d[0]), "+f"(d[1]), "+f"(d[2]), "+f"(d[3])
        : "r"(a[0]), "r"(a[1]), "r"(a[2]), "r"(a[3]), "r"(b0), "r"(b1));
}
__device__ __forceinline__ void ldm_x4(uint32_t* r, uint32_t addr) {
    asm volatile("ldmatrix.sync.aligned.m8n8.x4.shared.b16 {%0,%1,%2,%3}, [%4];"
                 : "=r"(r[0]), "=r"(r[1]), "=r"(r[2]), "=r"(r[3]) : "r"(addr));
}
__device__ __forceinline__ uint32_t smem_u32p(const void* p) {
    uint32_t a;
    asm("{ .reg .u64 t; cvta.to.shared.u64 t, %1; cvt.u32.u64 %0, t; }" : "=r"(a) : "l"(p));
    return a;
}
__device__ __forceinline__ void ld4h(const __half* p, float* f) {
    uint2 u = *(const uint2*)p;
    float2 fa = __half22float2(*(__half2*)&u.x);
    float2 fb = __half22float2(*(__half2*)&u.y);
    f[0] = fa.x; f[1] = fa.y; f[2] = fb.x; f[3] = fb.y;
}
__device__ __forceinline__ void st4h(__half* p, float a, float b, float c, float d) {
    __half2 h0 = __floats2half2_rn(a, b), h1 = __floats2half2_rn(c, d);
    uint2 u;
    u.x = *(uint32_t*)&h0; u.y = *(uint32_t*)&h1;
    *(uint2*)p = u;
}

// ---------------- fused prep #1 ----------------
__global__ void build_all(const float* __restrict__ wq, const float* __restrict__ wk,
                          const float* __restrict__ wv, const float* __restrict__ wao,
                          const float* __restrict__ bq, const float* __restrict__ bk,
                          const float* __restrict__ bv, const float* __restrict__ bao,
                          const float* __restrict__ wih, const float* __restrict__ whh,
                          const float* __restrict__ bih, const float* __restrict__ bhh) {
    int idx = blockIdx.x * blockDim.x + threadIdx.x;
    const float SC = 0.17677669529663687f;
    if (idx < 98304) {
        int n = idx >> 7, k = idx & 127;
        float v;
        if (n < 128) v = wq[n * 128 + k] * SC;
        else if (n < 256) v = wk[(n - 128) * 128 + k];
        else {
            int h = (n - 256) >> 7, d1 = (n - 256) & 127;
            float s = 0.f;
            for (int r = 0; r < 32; r++)
                s += wk[(h * 32 + r) * 128 + d1] * wq[(h * 32 + r) * 128 + k];
            v = s * SC;
        }
        g_WprojF[idx] = v;
    } else if (idx < 163840) {
        int i2 = idx - 98304;
        int n = i2 >> 9, m = i2 & 511;
        int h = m >> 7, d = m & 127;
        float s = 0.f;
        for (int r = 0; r < 32; r++)
            s += wao[n * 128 + h * 32 + r] * wv[(h * 32 + r) * 128 + d];
        g_Wav4F[i2] = s;
    } else if (idx < 164608) {
        int n = idx - 163840;
        float v;
        if (n < 128) v = bq[n] * SC;
        else if (n < 256) v = bk[n - 128];
        else {
            int h = (n - 256) >> 7, d1 = (n - 256) & 127;
            float s = 0.f;
            for (int r = 0; r < 32; r++)
                s += wk[(h * 32 + r) * 128 + d1] * bq[h * 32 + r];
            v = s * SC;
        }
        g_bproj[n] = v;
    } else if (idx < 164736) {
        int n = idx - 164608;
        float s = 0.f;
        for (int k = 0; k < 128; k++) s += wao[n * 128 + k] * bv[k];
        g_wbv[n] = s;
        g_bav[n] = s + bao[n];
    } else if (idx < 230272) {
        int i = idx - 164736;
        int n = i >> 8, k = i & 255;
        g_Wgrz[i] = (k < 128) ? wih[n * 128 + k] : whh[n * 128 + (k - 128)];
    } else if (idx < 230528) {
        int n = idx - 230272;
        g_brz[n] = bih[n] + bhh[n];
    } else if (idx < 230784) {
        int n = idx - 230528;
        g_bn[n] = (n < 128) ? bih[256 + n] : bhh[256 + (n - 128)];
    } else if (idx < 270784) {
        g_cnt[idx - 230784] = 0;
    }
}

// ---------------- fused prep #2: weights -> fp16 hi/lo chunk-images ----------------
__device__ __forceinline__ void img_write(const float* src, int i2, int K, int base) {
    int n = i2 / K, k = i2 % K;
    float v = src[i2];
    __half h = __float2half_rn(v);
    __half l = __float2half_rn(v - __half2float(h));
    int KC = K >> 6;
    size_t im = (size_t)(base + (n >> 7) * KC + (k >> 6));
    size_t word = im * 9216 + (n & 127) * 36 + ((k & 63) >> 1);
    unsigned short* p = (unsigned short*)g_img;
    p[word * 2 + (k & 1)] = __half_as_ushort(h);
    p[(word + 4608) * 2 + (k & 1)] = __half_as_ushort(l);
}
__global__ void prep_w_all(const float* __restrict__ wint, const float* __restrict__ wout,
                           const float* __restrict__ wih, const float* __restrict__ whh) {
    int idx = blockIdx.x * blockDim.x + threadIdx.x;
    if (idx < 98304)       img_write(g_WprojF, idx, 128, IMG_PROJ);
    else if (idx < 163840) img_write(g_Wav4F, idx - 98304, 512, IMG_WAV4);
    else if (idx < 229376) img_write(wint, idx - 163840, 128, IMG_WINT);
    else if (idx < 294912) img_write(wout, idx - 229376, 512, IMG_WOUT);
    else if (idx < 360448) img_write(g_Wgrz, idx - 294912, 256, IMG_GRZ);
    else if (idx < 376832) img_write(wih + 256 * 128, idx - 360448, 128, IMG_GN);
    else if (idx < 393216) img_write(whh + 256 * 128, idx - 376832, 128, IMG_GN + 2);
}

// x -> fp16 mirror + mh h-half; eattr -> fp16
__global__ void split_conv(const float* __restrict__ x, const float* __restrict__ eattr) {
    int idx = blockIdx.x * blockDim.x + threadIdx.x;
    if (idx < NN * 64) {
        float2 f = *(const float2*)(x + 2 * idx);
        __half2 h = __floats2half2_rn(f.x, f.y);
        *(__half2*)(g_xh + 2 * idx) = h;
        int w = idx >> 6, jw = idx & 63;
        *(__half2*)(g_mhh + (size_t)w * 256 + 128 + 2 * jw) = h;
    } else if (idx < NN * 64 + EE * 64) {
        size_t i2 = idx - NN * 64;
        float2 f = *(const float2*)(eattr + 2 * i2);
        *(__half2*)(g_eh + 2 * i2) = __floats2half2_rn(f.x, f.y);
    }
}

// ---------------- CSR build ----------------
__global__ void hist_kernel(const int* __restrict__ dst) {
    int i = blockIdx.x * blockDim.x + threadIdx.x;
    if (i < EE) atomicAdd(&g_cnt[dst[i]], 1);
}
__global__ void scan_kernel() {
    extern __shared__ int sbuf[];
    __shared__ int wsum[32];
    int t = threadIdx.x;
    for (int i = 0; i < 40; i++) {
        int j = i * 1024 + t;
        sbuf[j] = (j < NN) ? g_cnt[j] : 0;
    }
    __syncthreads();
    int s = 0;
    for (int i = 0; i < 40; i++) s += sbuf[t * 40 + i];
    int lane = t & 31, wid = t >> 5;
    int v = s;
#pragma unroll
    for (int off = 1; off < 32; off <<= 1) {
        int n = __shfl_up_sync(0xffffffffu, v, off);
        if (lane >= off) v += n;
    }
    if (lane == 31) wsum[wid] = v;
    __syncthreads();
    if (wid == 0) {
        int w = wsum[lane];
#pragma unroll
        for (int off = 1; off < 32; off <<= 1) {
            int n = __shfl_up_sync(0xffffffffu, w, off);
            if (lane >= off) w += n;
        }
        wsum[lane] = w;
    }
    __syncthreads();
    int r = v - s + (wid > 0 ? wsum[wid - 1] : 0);
    for (int i = 0; i < 40; i++) {
        int tmp = sbuf[t * 40 + i];
        sbuf[t * 40 + i] = r;
        r += tmp;
    }
    __syncthreads();
    for (int i = 0; i < 40; i++) {
        int j = i * 1024 + t;
        if (j < NN) { g_rowptr[j] = sbuf[j]; g_cur[j] = sbuf[j]; }
    }
    if (t == 1023) g_rowptr[NN] = wsum[31];
}
__global__ void scatter_kernel(const int* __restrict__ src, const int* __restrict__ dst) {
    int i = blockIdx.x * blockDim.x + threadIdx.x;
    if (i >= EE) return;
    int d = dst[i];
    int p = atomicAdd(&g_cur[d], 1);
    g_srcs[p] = src[i];
    g_eidxs[p] = i;
}

// ---------------- fp16 2-term mma GEMM (A single plane, B hi/lo), 2 CTAs/SM ----------------
// smem: A 4608 words (128x36), B 9216 words [hi|lo]. warp grid 2m x 4n; warp tile 64x32.
// OFMT: 0 fp32, 2 fp16. EPI: 1 bias, 2 bias+residual(fp32), 3 bias+gelu
template <int EPI, int OFMT>
__global__ void __launch_bounds__(256, 2) gemm_h(
    const __half* __restrict__ A, int rsw, int aoffy,
    const uint32_t* __restrict__ img,
    const float* __restrict__ bias, const float* __restrict__ res,
    void* __restrict__ outp, int M, int KC, int ldo)
{
    extern __shared__ uint32_t smw[];
    uint32_t* AS = smw;          // 4608
    uint32_t* BS = smw + 4608;   // 9216

    const int tid = threadIdx.x;
    const int warp = tid >> 5, lane = tid & 31;
    const int wm = warp >> 2, wn = warp & 3;
    const int lr = lane >> 2, lk = lane & 3;
    const int bm = blockIdx.x * 128;
    const int yoff = blockIdx.y * aoffy;

    float acc[4][4][4];
#pragma unroll
    for (int i = 0; i < 4; i++)
#pragma unroll
        for (int j = 0; j < 4; j++)
#pragma unroll
            for (int l = 0; l < 4; l++) acc[i][j][l] = 0.f;

    const uint32_t smb = smem_u32p(smw);
    const int a_row = ((lane >> 3) & 1) * 8 + (lane & 7);
    const int a_wrd = (lane >> 4) * 4;
    const uint32_t aAddr = smb + (uint32_t)(((wm * 64 + a_row) * 36 + a_wrd) * 4);
    const int b_row = ((lane >> 4) & 1) * 8 + (lane & 7);
    const int b_wrd = ((lane >> 3) & 1) * 4;
    const uint32_t bAddr = smb + 4608u * 4 + (uint32_t)(((wn * 32 + b_row) * 36 + b_wrd) * 4);

    int gr = bm + (tid >> 1);
    if (gr >= M) gr = M - 1;
    const int half = tid & 1;
    const uint32_t* asrc = (const uint32_t*)A + (size_t)gr * (rsw >> 1) + (yoff >> 1) + half * 16;
    uint32_t* da = AS + (tid >> 1) * 36 + half * 16;
    const uint4* bimg = (const uint4*)(img + (size_t)blockIdx.y * KC * 9216);

    for (int c = 0; c < KC; c++) {
        {
            const uint4* s4 = (const uint4*)(asrc + c * 32);
#pragma unroll
            for (int p = 0; p < 4; p++) *(uint4*)(da + p * 4) = s4[p];
        }
        {
            const uint4* bsrc4 = bimg + (size_t)c * 2304;
#pragma unroll
            for (int j = 0; j < 9; j++)
                *(uint4*)(BS + (j * 256 + tid) * 4) = bsrc4[j * 256 + tid];
        }
        __syncthreads();

#pragma unroll
        for (int s = 0; s < 4; s++) {
            uint32_t af[4][4];
#pragma unroll
            for (int mt = 0; mt < 4; mt++)
                ldm_x4(af[mt], aAddr + (mt * 576 + s * 8) * 4);
#pragma unroll
            for (int ntp = 0; ntp < 2; ntp++) {
                uint32_t bh[4], bl[4];
                ldm_x4(bh, bAddr + (ntp * 576 + s * 8) * 4);
                ldm_x4(bl, bAddr + 4608u * 4 + (ntp * 576 + s * 8) * 4);
#pragma unroll
                for (int hf = 0; hf < 2; hf++) {
                    int nt = ntp * 2 + hf;
#pragma unroll
                    for (int mt = 0; mt < 4; mt++) {
                        mma_f16(acc[mt][nt], af[mt], bh[2 * hf], bh[2 * hf + 1]);
                        mma_f16(acc[mt][nt], af[mt], bl[2 * hf], bl[2 * hf + 1]);
                    }
                }
            }
        }
        __syncthreads();
    }

    const int cbase = blockIdx.y * 128 + wn * 32;
#pragma unroll
    for (int mt = 0; mt < 4; mt++) {
        int r0 = bm + wm * 64 + mt * 16 + lr;
#pragma unroll
        for (int hf = 0; hf < 2; hf++) {
            int row = r0 + hf * 8;
            if (row >= M) continue;
            const float* rrow = (EPI == 2) ? (res + (size_t)row * ldo + cbase) : nullptr;
#pragma unroll
            for (int nt = 0; nt < 4; nt++) {
                int cl = nt * 8 + lk * 2;
                float v0 = acc[mt][nt][hf * 2 + 0];
                float v1 = acc[mt][nt][hf * 2 + 1];
                v0 += bias[cbase + cl];
                v1 += bias[cbase + cl + 1];
                if (EPI == 2) { v0 += rrow[cl]; v1 += rrow[cl + 1]; }
                if (EPI == 3) {
                    v0 = 0.5f * v0 * (1.f + erff(v0 * 0.70710678118654752f));
                    v1 = 0.5f * v1 * (1.f + erff(v1 * 0.70710678118654752f));
                }
                if (OFMT == 0)
                    *(float2*)((float*)outp + (size_t)row * ldo + cbase + cl) = make_float2(v0, v1);
                else
                    *(__half2*)((__half*)outp + (size_t)row * ldo + cbase + cl) = __floats2half2_rn(v0, v1);
            }
        }
    }
}

// ---------------- GAT: warp per node, fp16 operands ----------------
__global__ void gat2_kernel() {
    int w = (blockIdx.x * blockDim.x + threadIdx.x) >> 5;
    int lane = threadIdx.x & 31;
    if (w >= NN) return;
    const __half* pw = g_Ph + (size_t)w * 768;
    float q[4], qe[4][4], mx[4], smx[4], acc[4][4];
    ld4h(pw + lane * 4, q);
#pragma unroll
    for (int h = 0; h < 4; h++) {
        ld4h(pw + 256 + h * 128 + lane * 4, qe[h]);
#pragma unroll
        for (int j = 0; j < 4; j++) acc[h][j] = 0.f;
        mx[h] = -1e30f; smx[h] = 0.f;
    }
    const int myhead = lane >> 3;
    int beg = g_rowptr[w], end = g_rowptr[w + 1];
    for (int p = beg; p < end; p++) {
        int s = g_srcs[p], ei = g_eidxs[p];
        float kv[4], ev[4], xv[4], u[4];
        ld4h(g_Ph + (size_t)s * 768 + 128 + lane * 4, kv);
        ld4h(g_eh + (size_t)ei * 128 + lane * 4, ev);
        ld4h(g_xh + (size_t)s * 128 + lane * 4, xv);
        float qk = 0.f;
#pragma unroll
        for (int j = 0; j < 4; j++) {
            u[j] = xv[j] + ev[j];
            qk += q[j] * kv[j];
        }
        float d[4];
#pragma unroll
        for (int h = 0; h < 4; h++)
            d[h] = qe[h][0] * ev[0] + qe[h][1] * ev[1] + qe[h][2] * ev[2] + qe[h][3] * ev[3];
        d[myhead] += qk;
#pragma unroll
        for (int off = 16; off > 0; off >>= 1)
#pragma unroll
            for (int h = 0; h < 4; h++)
                d[h] += __shfl_xor_sync(0xffffffffu, d[h], off);
#pragma unroll
        for (int h = 0; h < 4; h++) {
            float a = d[h];
            float nm = fmaxf(mx[h], a);
            float csc = __expf(mx[h] - nm);
            float pe = __expf(a - nm);
            smx[h] = smx[h] * csc + pe;
#pragma unroll
            for (int j = 0; j < 4; j++)
                acc[h][j] = acc[h][j] * csc + pe * u[j];
            mx[h] = nm;
        }
    }
    __half* o = g_sxeh + (size_t)w * 512;
#pragma unroll
    for (int h = 0; h < 4; h++) {
        float inv = 1.f / (smx[h] + 1e-16f);
        st4h(o + h * 128 + lane * 4, acc[h][0] * inv, acc[h][1] * inv,
             acc[h][2] * inv, acc[h][3] * inv);
    }
}

// ---------------- LayerNorm: fp32 in; optional fp32 out; fp16 out ----------------
__global__ void ln_kernel(const float* __restrict__ in, const float* __restrict__ g,
                          const float* __restrict__ b, const float* __restrict__ corr,
                          float* __restrict__ outF, __half* __restrict__ out16,
                          int st16, int off16) {
    int w = (blockIdx.x * blockDim.x + threadIdx.x) >> 5;
    int lane = threadIdx.x & 31;
    if (w >= NN) return;
    const float* row = in + (size_t)w * 128;
    float4 v4 = *(const float4*)(row + lane * 4);
    float v[4] = {v4.x, v4.y, v4.z, v4.w};
    if (corr && g_rowptr[w] == g_rowptr[w + 1]) {
        float4 c4 = *(const float4*)(corr + lane * 4);
        v[0] -= c4.x; v[1] -= c4.y; v[2] -= c4.z; v[3] -= c4.w;
    }
    float s = v[0] + v[1] + v[2] + v[3];
#pragma unroll
    for (int off = 16; off > 0; off >>= 1) s += __shfl_xor_sync(0xffffffffu, s, off);
    float mean = s * (1.f / 128.f), s2 = 0.f;
#pragma unroll
    for (int j = 0; j < 4; j++) { float d = v[j] - mean; s2 += d * d; }
#pragma unroll
    for (int off = 16; off > 0; off >>= 1) s2 += __shfl_xor_sync(0xffffffffu, s2, off);
    float inv = rsqrtf(s2 * (1.f / 128.f) + 1e-12f);
    float4 g4 = *(const float4*)(g + lane * 4);
    float4 b4 = *(const float4*)(b + lane * 4);
    float o0 = g4.x * (v[0] - mean) * inv + b4.x;
    float o1 = g4.y * (v[1] - mean) * inv + b4.y;
    float o2 = g4.z * (v[2] - mean) * inv + b4.z;
    float o3 = g4.w * (v[3] - mean) * inv + b4.w;
    if (outF)
        *(float4*)(outF + (size_t)w * 128 + lane * 4) = make_float4(o0, o1, o2, o3);
    st4h(out16 + (size_t)w * st16 + off16 + lane * 4, o0, o1, o2, o3);
}

// ---------------- GRU + LN3 ----------------
__global__ void gru_ln_kernel(const float* __restrict__ hprev,
                              const float* __restrict__ lng, const float* __restrict__ lnb,
                              float* __restrict__ xout) {
    int w = (blockIdx.x * blockDim.x + threadIdx.x) >> 5;
    int lane = threadIdx.x & 31;
    if (w >= NN) return;
    float4 r4 = *(const float4*)(g_grz + (size_t)w * 256 + lane * 4);
    float4 z4 = *(const float4*)(g_grz + (size_t)w * 256 + 128 + lane * 4);
    float4 ni4 = *(const float4*)(g_gn + (size_t)w * 256 + lane * 4);
    float4 nh4 = *(const float4*)(g_gn + (size_t)w * 256 + 128 + lane * 4);
    float4 h4 = *(const float4*)(hprev + (size_t)w * 128 + lane * 4);
    float rr[4] = {r4.x, r4.y, r4.z, r4.w};
    float zz[4] = {z4.x, z4.y, z4.z, z4.w};
    float ni[4] = {ni4.x, ni4.y, ni4.z, ni4.w};
    float nh[4] = {nh4.x, nh4.y, nh4.z, nh4.w};
    float hv[4] = {h4.x, h4.y, h4.z, h4.w};
    float hn[4], s = 0.f;
#pragma unroll
    for (int j = 0; j < 4; j++) {
        float r = 1.f / (1.f + expf(-rr[j]));
        float z = 1.f / (1.f + expf(-zz[j]));
        float n = tanhf(ni[j] + r * nh[j]);
        hn[j] = (1.f - z) * n + z * hv[j];
        s += hn[j];
    }
    *(float4*)(g_h + (size_t)w * 128 + lane * 4) = make_float4(hn[0], hn[1], hn[2], hn[3]);
    st4h(g_mhh + (size_t)w * 256 + 128 + lane * 4, hn[0], hn[1], hn[2], hn[3]);
#pragma unroll
    for (int off = 16; off > 0; off >>= 1) s += __shfl_xor_sync(0xffffffffu, s, off);
    float mean = s * (1.f / 128.f), s2 = 0.f;
#pragma unroll
    for (int j = 0; j < 4; j++) { float d = hn[j] - mean; s2 += d * d; }
#pragma unroll
    for (int off = 16; off > 0; off >>= 1) s2 += __shfl_xor_sync(0xffffffffu, s2, off);
    float inv = rsqrtf(s2 * (1.f / 128.f) + 1e-12f);
    float4 g4 = *(const float4*)(lng + lane * 4);
    float4 b4 = *(const float4*)(lnb + lane * 4);
    float o0 = g4.x * (hn[0] - mean) * inv + b4.x;
    float o1 = g4.y * (hn[1] - mean) * inv + b4.y;
    float o2 = g4.z * (hn[2] - mean) * inv + b4.z;
    float o3 = g4.w * (hn[3] - mean) * inv + b4.w;
    *(float4*)(xout + (size_t)w * 128 + lane * 4) = make_float4(o0, o1, o2, o3);
    st4h(g_xh + (size_t)w * 128 + lane * 4, o0, o1, o2, o3);
}

// ---------------- host ----------------
static void* sym_addr(const void* symbol) {
    void* p = nullptr;
    cudaGetSymbolAddress(&p, symbol);
    return p;
}

extern "C" void kernel_launch(void* const* d_in, const int* in_sizes, int n_in,
                              void* d_out, int out_size) {
    (void)in_sizes; (void)n_in; (void)out_size;
    const float* x     = (const float*)d_in[0];
    const int*   ei    = (const int*)d_in[1];
    const float* eattr = (const float*)d_in[2];
    const float* wq  = (const float*)d_in[3];  const float* bq  = (const float*)d_in[4];
    const float* wk  = (const float*)d_in[5];  const float* bk  = (const float*)d_in[6];
    const float* wv  = (const float*)d_in[7];  const float* bv  = (const float*)d_in[8];
    const float* wao = (const float*)d_in[9];  const float* bao = (const float*)d_in[10];
    const float* ln1g = (const float*)d_in[11]; const float* ln1b = (const float*)d_in[12];
    const float* wint = (const float*)d_in[13]; const float* bint = (const float*)d_in[14];
    const float* wout = (const float*)d_in[15]; const float* bout = (const float*)d_in[16];
    const float* ln2g = (const float*)d_in[17]; const float* ln2b = (const float*)d_in[18];
    const float* wih = (const float*)d_in[19];  const float* whh = (const float*)d_in[20];
    const float* bih = (const float*)d_in[21];  const float* bhh = (const float*)d_in[22];
    const float* ln3g = (const float*)d_in[23]; const float* ln3b = (const float*)d_in[24];
    float* out = (float*)d_out;

    __half* pPh   = (__half*)sym_addr(g_Ph);
    __half* pSxeh = (__half*)sym_addr(g_sxeh);
    __half* pXh   = (__half*)sym_addr(g_xh);
    __half* pAtth = (__half*)sym_addr(g_atth);
    __half* pInth = (__half*)sym_addr(g_inth);
    __half* pMhh  = (__half*)sym_addr(g_mhh);
    float* pPre  = (float*)sym_addr(g_pre);
    float* pAtt  = (float*)sym_addr(g_att);
    float* pGrz  = (float*)sym_addr(g_grz);
    float* pGn   = (float*)sym_addr(g_gn);
    float* pH    = (float*)sym_addr(g_h);
    float* pX    = (float*)sym_addr(g_x);
    float* pBproj = (float*)sym_addr(g_bproj);
    float* pBav   = (float*)sym_addr(g_bav);
    float* pWbv   = (float*)sym_addr(g_wbv);
    float* pBrz   = (float*)sym_addr(g_brz);
    float* pBn    = (float*)sym_addr(g_bn);
    uint32_t* pImg = (uint32_t*)sym_addr(g_img);

    const int* srcp = ei;
    const int* dstp = ei + EE;

    const int SMB = 13824 * 4;  // 55296 B
    cudaFuncSetAttribute(gemm_h<1, 2>, cudaFuncAttributeMaxDynamicSharedMemorySize, SMB);
    cudaFuncSetAttribute(gemm_h<2, 0>, cudaFuncAttributeMaxDynamicSharedMemorySize, SMB);
    cudaFuncSetAttribute(gemm_h<3, 2>, cudaFuncAttributeMaxDynamicSharedMemorySize, SMB);
    cudaFuncSetAttribute(gemm_h<1, 0>, cudaFuncAttributeMaxDynamicSharedMemorySize, SMB);
    cudaFuncSetAttribute(scan_kernel, cudaFuncAttributeMaxDynamicSharedMemorySize, 40960 * 4);

    const int MT = (NN + 127) / 128;
    const int RG = (NN + 7) / 8;

    // launches 1-3 prep; launch 4 = proj GEMM (ncu slot)
    build_all<<<(270784 + 255) / 256, 256>>>(wq, wk, wv, wao, bq, bk, bv, bao, wih, whh, bih, bhh);
    prep_w_all<<<(393216 + 255) / 256, 256>>>(wint, wout, wih, whh);
    split_conv<<<(NN * 64 + EE * 64 + 255) / 256, 256>>>(x, eattr);
    gemm_h<1, 2><<<dim3(MT, 6), 256, SMB>>>(pXh, 128, 0,
        pImg + (size_t)IMG_PROJ * 9216, pBproj, nullptr, pPh, NN, 2, 768);
    hist_kernel<<<(EE + 255) / 256, 256>>>(dstp);
    scan_kernel<<<1, 1024, 40960 * 4>>>();
    scatter_kernel<<<(EE + 255) / 256, 256>>>(srcp, dstp);

    for (int t = 0; t < 3; t++) {
        const float* xcur = (t == 0) ? x : pX;
        const float* hcur = (t == 0) ? x : pH;
        if (t > 0)
            gemm_h<1, 2><<<dim3(MT, 6), 256, SMB>>>(pXh, 128, 0,
                pImg + (size_t)IMG_PROJ * 9216, pBproj, nullptr, pPh, NN, 2, 768);
        gat2_kernel<<<RG, 256>>>();
        gemm_h<2, 0><<<dim3(MT, 1), 256, SMB>>>(pSxeh, 512, 0,
            pImg + (size_t)IMG_WAV4 * 9216, pBav, xcur, pPre, NN, 8, 128);
        ln_kernel<<<RG, 256>>>(pPre, ln1g, ln1b, pWbv, pAtt, pAtth, 128, 0);
        gemm_h<3, 2><<<dim3(MT, 4), 256, SMB>>>(pAtth, 128, 0,
            pImg + (size_t)IMG_WINT * 9216, bint, nullptr, pInth, NN, 2, 512);
        gemm_h<2, 0><<<dim3(MT, 1), 256, SMB>>>(pInth, 512, 0,
            pImg + (size_t)IMG_WOUT * 9216, bout, pAtt, pPre, NN, 8, 128);
        ln_kernel<<<RG, 256>>>(pPre, ln2g, ln2b, nullptr, nullptr, pMhh, 256, 0);
        gemm_h<1, 0><<<dim3(MT, 2), 256, SMB>>>(pMhh, 256, 0,
            pImg + (size_t)IMG_GRZ * 9216, pBrz, nullptr, pGrz, NN, 4, 256);
        gemm_h<1, 0><<<dim3(MT, 2), 256, SMB>>>(pMhh, 256, 128,
            pImg + (size_t)IMG_GN * 9216, pBn, nullptr, pGn, NN, 2, 256);
        gru_ln_kernel<<<RG, 256>>>(hcur, ln3g, ln3b, (t == 2) ? out : pX);
    }
}

// round 10
// speedup vs baseline: 1.9637x; 1.0165x over previous
#include <cuda_runtime.h>
#include <cuda_fp16.h>
#include <math.h>
#include <stdint.h>

#define NN 40000
#define EE 320000

// ---------------- device scratch ----------------
__device__ __half g_P5[(size_t)NN * 640];      // fp16 [q(128) | qe(512)] per dst node
__device__ __half g_kx[(size_t)NN * 256];      // fp16 [k(128) | x(128)] per src node
__device__ __half g_ehs[(size_t)EE * 128];     // fp16 edge_attr in CSR order
__device__ __half g_sxeh[(size_t)NN * 512];    // fp16 GAT output
__device__ __half g_xh[NN * 128];              // fp16 x mirror (GEMM A)
__device__ __half g_atth[NN * 128];
__device__ __half g_inth[(size_t)NN * 512];
__device__ __half g_mhh[(size_t)NN * 256];     // fp16 [m|h]
__device__ float g_pre[NN * 128];
__device__ float g_att[NN * 128];
__device__ float g_grz[(size_t)NN * 256];
__device__ float g_gn[(size_t)NN * 256];
__device__ float g_h[NN * 128];
__device__ float g_x[NN * 128];
__device__ float g_WprojF[768 * 128];          // [k | q*SC | M]
__device__ float g_Wav4F[128 * 512];
__device__ float g_Wgrz[256 * 256];
__device__ float g_bproj[768], g_bav[128], g_wbv[128], g_brz[256], g_bn[256];
__device__ uint32_t g_img[(size_t)48 * 9216];
__device__ int g_cnt[NN], g_rowptr[NN + 1], g_cur[NN], g_srcs[EE], g_eidxs[EE];

#define IMG_PROJ 0
#define IMG_WAV4 12
#define IMG_WINT 20
#define IMG_WOUT 28
#define IMG_GRZ  36
#define IMG_GN   44

// ---------------- helpers ----------------
__device__ __forceinline__ void mma_f16(float* d, const uint32_t* a, uint32_t b0, uint32_t b1) {
    asm volatile(
        "mma.sync.aligned.m16n8k16.row.col.f32.f16.f16.f32 "
        "{%0,%1,%2,%3}, {%4,%5,%6,%7}, {%8,%9}, {%0,%1,%2,%3};"
        : "+f"(d[0]), "+f"(d[1]), "+f"(d[2]), "+f"(d[3])
        : "r"(a[0]), "r"(a[1]), "r"(a[2]), "r"(a[3]), "r"(b0), "r"(b1));
}
__device__ __forceinline__ void ldm_x4(uint32_t* r, uint32_t addr) {
    asm volatile("ldmatrix.sync.aligned.m8n8.x4.shared.b16 {%0,%1,%2,%3}, [%4];"
                 : "=r"(r[0]), "=r"(r[1]), "=r"(r[2]), "=r"(r[3]) : "r"(addr));
}
__device__ __forceinline__ uint32_t smem_u32p(const void* p) {
    uint32_t a;
    asm("{ .reg .u64 t; cvta.to.shared.u64 t, %1; cvt.u32.u64 %0, t; }" : "=r"(a) : "l"(p));
    return a;
}
__device__ __forceinline__ void ld4h(const __half* p, float* f) {
    uint2 u = *(const uint2*)p;
    float2 fa = __half22float2(*(__half2*)&u.x);
    float2 fb = __half22float2(*(__half2*)&u.y);
    f[0] = fa.x; f[1] = fa.y; f[2] = fb.x; f[3] = fb.y;
}
__device__ __forceinline__ void st4h(__half* p, float a, float b, float c, float d) {
    __half2 h0 = __floats2half2_rn(a, b), h1 = __floats2half2_rn(c, d);
    uint2 u;
    u.x = *(uint32_t*)&h0; u.y = *(uint32_t*)&h1;
    *(uint2*)p = u;
}

// ---------------- fused prep #1 ----------------
__global__ void build_all(const float* __restrict__ wq, const float* __restrict__ wk,
                          const float* __restrict__ wv, const float* __restrict__ wao,
                          const float* __restrict__ bq, const float* __restrict__ bk,
                          const float* __restrict__ bv, const float* __restrict__ bao,
                          const float* __restrict__ wih, const float* __restrict__ whh,
                          const float* __restrict__ bih, const float* __restrict__ bhh) {
    int idx = blockIdx.x * blockDim.x + threadIdx.x;
    const float SC = 0.17677669529663687f;
    if (idx < 98304) {                       // WprojF [k | q*SC | M]
        int n = idx >> 7, k = idx & 127;
        float v;
        if (n < 128) v = wk[n * 128 + k];
        else if (n < 256) v = wq[(n - 128) * 128 + k] * SC;
        else {
            int h = (n - 256) >> 7, d1 = (n - 256) & 127;
            float s = 0.f;
            for (int r = 0; r < 32; r++)
                s += wk[(h * 32 + r) * 128 + d1] * wq[(h * 32 + r) * 128 + k];
            v = s * SC;
        }
        g_WprojF[idx] = v;
    } else if (idx < 163840) {
        int i2 = idx - 98304;
        int n = i2 >> 9, m = i2 & 511;
        int h = m >> 7, d = m & 127;
        float s = 0.f;
        for (int r = 0; r < 32; r++)
            s += wao[n * 128 + h * 32 + r] * wv[(h * 32 + r) * 128 + d];
        g_Wav4F[i2] = s;
    } else if (idx < 164608) {               // bproj [bk | bq*SC | bM]
        int n = idx - 163840;
        float v;
        if (n < 128) v = bk[n];
        else if (n < 256) v = bq[n - 128] * SC;
        else {
            int h = (n - 256) >> 7, d1 = (n - 256) & 127;
            float s = 0.f;
            for (int r = 0; r < 32; r++)
                s += wk[(h * 32 + r) * 128 + d1] * bq[h * 32 + r];
            v = s * SC;
        }
        g_bproj[n] = v;
    } else if (idx < 164736) {
        int n = idx - 164608;
        float s = 0.f;
        for (int k = 0; k < 128; k++) s += wao[n * 128 + k] * bv[k];
        g_wbv[n] = s;
        g_bav[n] = s + bao[n];
    } else if (idx < 230272) {
        int i = idx - 164736;
        int n = i >> 8, k = i & 255;
        g_Wgrz[i] = (k < 128) ? wih[n * 128 + k] : whh[n * 128 + (k - 128)];
    } else if (idx < 230528) {
        int n = idx - 230272;
        g_brz[n] = bih[n] + bhh[n];
    } else if (idx < 230784) {
        int n = idx - 230528;
        g_bn[n] = (n < 128) ? bih[256 + n] : bhh[256 + (n - 128)];
    } else if (idx < 270784) {
        g_cnt[idx - 230784] = 0;
    }
}

// ---------------- fused prep #2: weights -> fp16 hi/lo chunk-images ----------------
__device__ __forceinline__ void img_write(const float* src, int i2, int K, int base) {
    int n = i2 / K, k = i2 % K;
    float v = src[i2];
    __half h = __float2half_rn(v);
    __half l = __float2half_rn(v - __half2float(h));
    int KC = K >> 6;
    size_t im = (size_t)(base + (n >> 7) * KC + (k >> 6));
    size_t word = im * 9216 + (n & 127) * 36 + ((k & 63) >> 1);
    unsigned short* p = (unsigned short*)g_img;
    p[word * 2 + (k & 1)] = __half_as_ushort(h);
    p[(word + 4608) * 2 + (k & 1)] = __half_as_ushort(l);
}
__global__ void prep_w_all(const float* __restrict__ wint, const float* __restrict__ wout,
                           const float* __restrict__ wih, const float* __restrict__ whh) {
    int idx = blockIdx.x * blockDim.x + threadIdx.x;
    if (idx < 98304)       img_write(g_WprojF, idx, 128, IMG_PROJ);
    else if (idx < 163840) img_write(g_Wav4F, idx - 98304, 512, IMG_WAV4);
    else if (idx < 229376) img_write(wint, idx - 163840, 128, IMG_WINT);
    else if (idx < 294912) img_write(wout, idx - 229376, 512, IMG_WOUT);
    else if (idx < 360448) img_write(g_Wgrz, idx - 294912, 256, IMG_GRZ);
    else if (idx < 376832) img_write(wih + 256 * 128, idx - 360448, 128, IMG_GN);
    else if (idx < 393216) img_write(whh + 256 * 128, idx - 376832, 128, IMG_GN + 2);
}

// x -> fp16 mirror + mh h-half + kx x-half
__global__ void split_conv(const float* __restrict__ x) {
    int idx = blockIdx.x * blockDim.x + threadIdx.x;
    if (idx >= NN * 64) return;
    float2 f = *(const float2*)(x + 2 * idx);
    __half2 h = __floats2half2_rn(f.x, f.y);
    *(__half2*)(g_xh + 2 * idx) = h;
    int w = idx >> 6, jw = idx & 63;
    *(__half2*)(g_mhh + (size_t)w * 256 + 128 + 2 * jw) = h;
    *(__half2*)(g_kx + (size_t)w * 256 + 128 + 2 * jw) = h;
}

// ---------------- CSR build ----------------
__global__ void hist_kernel(const int* __restrict__ dst) {
    int i = blockIdx.x * blockDim.x + threadIdx.x;
    if (i < EE) atomicAdd(&g_cnt[dst[i]], 1);
}
__global__ void scan_kernel() {
    extern __shared__ int sbuf[];
    __shared__ int wsum[32];
    int t = threadIdx.x;
    for (int i = 0; i < 40; i++) {
        int j = i * 1024 + t;
        sbuf[j] = (j < NN) ? g_cnt[j] : 0;
    }
    __syncthreads();
    int s = 0;
    for (int i = 0; i < 40; i++) s += sbuf[t * 40 + i];
    int lane = t & 31, wid = t >> 5;
    int v = s;
#pragma unroll
    for (int off = 1; off < 32; off <<= 1) {
        int n = __shfl_up_sync(0xffffffffu, v, off);
        if (lane >= off) v += n;
    }
    if (lane == 31) wsum[wid] = v;
    __syncthreads();
    if (wid == 0) {
        int w = wsum[lane];
#pragma unroll
        for (int off = 1; off < 32; off <<= 1) {
            int n = __shfl_up_sync(0xffffffffu, w, off);
            if (lane >= off) w += n;
        }
        wsum[lane] = w;
    }
    __syncthreads();
    int r = v - s + (wid > 0 ? wsum[wid - 1] : 0);
    for (int i = 0; i < 40; i++) {
        int tmp = sbuf[t * 40 + i];
        sbuf[t * 40 + i] = r;
        r += tmp;
    }
    __syncthreads();
    for (int i = 0; i < 40; i++) {
        int j = i * 1024 + t;
        if (j < NN) { g_rowptr[j] = sbuf[j]; g_cur[j] = sbuf[j]; }
    }
    if (t == 1023) g_rowptr[NN] = wsum[31];
}
__global__ void scatter_kernel(const int* __restrict__ src, const int* __restrict__ dst) {
    int i = blockIdx.x * blockDim.x + threadIdx.x;
    if (i >= EE) return;
    int d = dst[i];
    int p = atomicAdd(&g_cur[d], 1);
    g_srcs[p] = src[i];
    g_eidxs[p] = i;
}
// gather eattr into CSR order (fp16) — one-time
__global__ void gather_e(const float* __restrict__ eattr) {
    size_t idx = (size_t)blockIdx.x * blockDim.x + threadIdx.x;
    if (idx >= (size_t)EE * 64) return;
    size_t p = idx >> 6;
    int j = (int)(idx & 63);
    int ei = g_eidxs[p];
    float2 f = *(const float2*)(eattr + (size_t)ei * 128 + 2 * j);
    *(__half2*)(g_ehs + p * 128 + 2 * j) = __floats2half2_rn(f.x, f.y);
}

// ---------------- fp16 2-term mma GEMM (A single plane, B hi/lo), 2 CTAs/SM ----------------
template <int EPI, int OFMT>
__global__ void __launch_bounds__(256, 2) gemm_h(
    const __half* __restrict__ A, int rsw, int aoffy,
    const uint32_t* __restrict__ img,
    const float* __restrict__ bias, const float* __restrict__ res,
    void* __restrict__ outp, int M, int KC, int ldo)
{
    extern __shared__ uint32_t smw[];
    uint32_t* AS = smw;
    uint32_t* BS = smw + 4608;

    const int tid = threadIdx.x;
    const int warp = tid >> 5, lane = tid & 31;
    const int wm = warp >> 2, wn = warp & 3;
    const int lr = lane >> 2, lk = lane & 3;
    const int bm = blockIdx.x * 128;
    const int yoff = blockIdx.y * aoffy;

    float acc[4][4][4];
#pragma unroll
    for (int i = 0; i < 4; i++)
#pragma unroll
        for (int j = 0; j < 4; j++)
#pragma unroll
            for (int l = 0; l < 4; l++) acc[i][j][l] = 0.f;

    const uint32_t smb = smem_u32p(smw);
    const int a_row = ((lane >> 3) & 1) * 8 + (lane & 7);
    const int a_wrd = (lane >> 4) * 4;
    const uint32_t aAddr = smb + (uint32_t)(((wm * 64 + a_row) * 36 + a_wrd) * 4);
    const int b_row = ((lane >> 4) & 1) * 8 + (lane & 7);
    const int b_wrd = ((lane >> 3) & 1) * 4;
    const uint32_t bAddr = smb + 4608u * 4 + (uint32_t)(((wn * 32 + b_row) * 36 + b_wrd) * 4);

    int gr = bm + (tid >> 1);
    if (gr >= M) gr = M - 1;
    const int half = tid & 1;
    const uint32_t* asrc = (const uint32_t*)A + (size_t)gr * (rsw >> 1) + (yoff >> 1) + half * 16;
    uint32_t* da = AS + (tid >> 1) * 36 + half * 16;
    const uint4* bimg = (const uint4*)(img + (size_t)blockIdx.y * KC * 9216);

    for (int c = 0; c < KC; c++) {
        {
            const uint4* s4 = (const uint4*)(asrc + c * 32);
#pragma unroll
            for (int p = 0; p < 4; p++) *(uint4*)(da + p * 4) = s4[p];
        }
        {
            const uint4* bsrc4 = bimg + (size_t)c * 2304;
#pragma unroll
            for (int j = 0; j < 9; j++)
                *(uint4*)(BS + (j * 256 + tid) * 4) = bsrc4[j * 256 + tid];
        }
        __syncthreads();

#pragma unroll
        for (int s = 0; s < 4; s++) {
            uint32_t af[4][4];
#pragma unroll
            for (int mt = 0; mt < 4; mt++)
                ldm_x4(af[mt], aAddr + (mt * 576 + s * 8) * 4);
#pragma unroll
            for (int ntp = 0; ntp < 2; ntp++) {
                uint32_t bh[4], bl[4];
                ldm_x4(bh, bAddr + (ntp * 576 + s * 8) * 4);
                ldm_x4(bl, bAddr + 4608u * 4 + (ntp * 576 + s * 8) * 4);
#pragma unroll
                for (int hf = 0; hf < 2; hf++) {
                    int nt = ntp * 2 + hf;
#pragma unroll
                    for (int mt = 0; mt < 4; mt++) {
                        mma_f16(acc[mt][nt], af[mt], bh[2 * hf], bh[2 * hf + 1]);
                        mma_f16(acc[mt][nt], af[mt], bl[2 * hf], bl[2 * hf + 1]);
                    }
                }
            }
        }
        __syncthreads();
    }

    const int cbase = blockIdx.y * 128 + wn * 32;
#pragma unroll
    for (int mt = 0; mt < 4; mt++) {
        int r0 = bm + wm * 64 + mt * 16 + lr;
#pragma unroll
        for (int hf = 0; hf < 2; hf++) {
            int row = r0 + hf * 8;
            if (row >= M) continue;
            const float* rrow = (EPI == 2) ? (res + (size_t)row * ldo + cbase) : nullptr;
#pragma unroll
            for (int nt = 0; nt < 4; nt++) {
                int cl = nt * 8 + lk * 2;
                float v0 = acc[mt][nt][hf * 2 + 0];
                float v1 = acc[mt][nt][hf * 2 + 1];
                v0 += bias[cbase + cl];
                v1 += bias[cbase + cl + 1];
                if (EPI == 2) { v0 += rrow[cl]; v1 += rrow[cl + 1]; }
                if (EPI == 3) {
                    v0 = 0.5f * v0 * (1.f + erff(v0 * 0.70710678118654752f));
                    v1 = 0.5f * v1 * (1.f + erff(v1 * 0.70710678118654752f));
                }
                if (OFMT == 0)
                    *(float2*)((float*)outp + (size_t)row * ldo + cbase + cl) = make_float2(v0, v1);
                else
                    *(__half2*)((__half*)outp + (size_t)row * ldo + cbase + cl) = __floats2half2_rn(v0, v1);
            }
        }
    }
}

// ---------------- GAT: warp per node; kx combined gather + sequential ev ----------------
__global__ void gat2_kernel() {
    int w = (blockIdx.x * blockDim.x + threadIdx.x) >> 5;
    int lane = threadIdx.x & 31;
    if (w >= NN) return;
    const __half* pw = g_P5 + (size_t)w * 640;
    float q[4], qe[4][4], mx[4], smx[4], acc[4][4];
    ld4h(pw + lane * 4, q);
#pragma unroll
    for (int h = 0; h < 4; h++) {
        ld4h(pw + 128 + h * 128 + lane * 4, qe[h]);
#pragma unroll
        for (int j = 0; j < 4; j++) acc[h][j] = 0.f;
        mx[h] = -1e30f; smx[h] = 0.f;
    }
    const int myhead = lane >> 3;
    int beg = g_rowptr[w], end = g_rowptr[w + 1];
    for (int p = beg; p < end; p++) {
        int s = g_srcs[p];
        const __half* kxp = g_kx + (size_t)s * 256;
        float kv[4], xv[4], ev[4], u[4];
        ld4h(kxp + lane * 4, kv);
        ld4h(kxp + 128 + lane * 4, xv);
        ld4h(g_ehs + (size_t)p * 128 + lane * 4, ev);
        float qk = 0.f;
#pragma unroll
        for (int j = 0; j < 4; j++) {
            u[j] = xv[j] + ev[j];
            qk += q[j] * kv[j];
        }
        float d[4];
#pragma unroll
        for (int h = 0; h < 4; h++)
            d[h] = qe[h][0] * ev[0] + qe[h][1] * ev[1] + qe[h][2] * ev[2] + qe[h][3] * ev[3];
        d[myhead] += qk;
#pragma unroll
        for (int off = 16; off > 0; off >>= 1)
#pragma unroll
            for (int h = 0; h < 4; h++)
                d[h] += __shfl_xor_sync(0xffffffffu, d[h], off);
#pragma unroll
        for (int h = 0; h < 4; h++) {
            float a = d[h];
            float nm = fmaxf(mx[h], a);
            float csc = __expf(mx[h] - nm);
            float pe = __expf(a - nm);
            smx[h] = smx[h] * csc + pe;
#pragma unroll
            for (int j = 0; j < 4; j++)
                acc[h][j] = acc[h][j] * csc + pe * u[j];
            mx[h] = nm;
        }
    }
    __half* o = g_sxeh + (size_t)w * 512;
#pragma unroll
    for (int h = 0; h < 4; h++) {
        float inv = 1.f / (smx[h] + 1e-16f);
        st4h(o + h * 128 + lane * 4, acc[h][0] * inv, acc[h][1] * inv,
             acc[h][2] * inv, acc[h][3] * inv);
    }
}

// ---------------- LayerNorm ----------------
__global__ void ln_kernel(const float* __restrict__ in, const float* __restrict__ g,
                          const float* __restrict__ b, const float* __restrict__ corr,
                          float* __restrict__ outF, __half* __restrict__ out16,
                          int st16, int off16) {
    int w = (blockIdx.x * blockDim.x + threadIdx.x) >> 5;
    int lane = threadIdx.x & 31;
    if (w >= NN) return;
    const float* row = in + (size_t)w * 128;
    float4 v4 = *(const float4*)(row + lane * 4);
    float v[4] = {v4.x, v4.y, v4.z, v4.w};
    if (corr && g_rowptr[w] == g_rowptr[w + 1]) {
        float4 c4 = *(const float4*)(corr + lane * 4);
        v[0] -= c4.x; v[1] -= c4.y; v[2] -= c4.z; v[3] -= c4.w;
    }
    float s = v[0] + v[1] + v[2] + v[3];
#pragma unroll
    for (int off = 16; off > 0; off >>= 1) s += __shfl_xor_sync(0xffffffffu, s, off);
    float mean = s * (1.f / 128.f), s2 = 0.f;
#pragma unroll
    for (int j = 0; j < 4; j++) { float d = v[j] - mean; s2 += d * d; }
#pragma unroll
    for (int off = 16; off > 0; off >>= 1) s2 += __shfl_xor_sync(0xffffffffu, s2, off);
    float inv = rsqrtf(s2 * (1.f / 128.f) + 1e-12f);
    float4 g4 = *(const float4*)(g + lane * 4);
    float4 b4 = *(const float4*)(b + lane * 4);
    float o0 = g4.x * (v[0] - mean) * inv + b4.x;
    float o1 = g4.y * (v[1] - mean) * inv + b4.y;
    float o2 = g4.z * (v[2] - mean) * inv + b4.z;
    float o3 = g4.w * (v[3] - mean) * inv + b4.w;
    if (outF)
        *(float4*)(outF + (size_t)w * 128 + lane * 4) = make_float4(o0, o1, o2, o3);
    st4h(out16 + (size_t)w * st16 + off16 + lane * 4, o0, o1, o2, o3);
}

// ---------------- GRU + LN3 ----------------
__global__ void gru_ln_kernel(const float* __restrict__ hprev,
                              const float* __restrict__ lng, const float* __restrict__ lnb,
                              float* __restrict__ xout) {
    int w = (blockIdx.x * blockDim.x + threadIdx.x) >> 5;
    int lane = threadIdx.x & 31;
    if (w >= NN) return;
    float4 r4 = *(const float4*)(g_grz + (size_t)w * 256 + lane * 4);
    float4 z4 = *(const float4*)(g_grz + (size_t)w * 256 + 128 + lane * 4);
    float4 ni4 = *(const float4*)(g_gn + (size_t)w * 256 + lane * 4);
    float4 nh4 = *(const float4*)(g_gn + (size_t)w * 256 + 128 + lane * 4);
    float4 h4 = *(const float4*)(hprev + (size_t)w * 128 + lane * 4);
    float rr[4] = {r4.x, r4.y, r4.z, r4.w};
    float zz[4] = {z4.x, z4.y, z4.z, z4.w};
    float ni[4] = {ni4.x, ni4.y, ni4.z, ni4.w};
    float nh[4] = {nh4.x, nh4.y, nh4.z, nh4.w};
    float hv[4] = {h4.x, h4.y, h4.z, h4.w};
    float hn[4], s = 0.f;
#pragma unroll
    for (int j = 0; j < 4; j++) {
        float r = 1.f / (1.f + expf(-rr[j]));
        float z = 1.f / (1.f + expf(-zz[j]));
        float n = tanhf(ni[j] + r * nh[j]);
        hn[j] = (1.f - z) * n + z * hv[j];
        s += hn[j];
    }
    *(float4*)(g_h + (size_t)w * 128 + lane * 4) = make_float4(hn[0], hn[1], hn[2], hn[3]);
    st4h(g_mhh + (size_t)w * 256 + 128 + lane * 4, hn[0], hn[1], hn[2], hn[3]);
#pragma unroll
    for (int off = 16; off > 0; off >>= 1) s += __shfl_xor_sync(0xffffffffu, s, off);
    float mean = s * (1.f / 128.f), s2 = 0.f;
#pragma unroll
    for (int j = 0; j < 4; j++) { float d = hn[j] - mean; s2 += d * d; }
#pragma unroll
    for (int off = 16; off > 0; off >>= 1) s2 += __shfl_xor_sync(0xffffffffu, s2, off);
    float inv = rsqrtf(s2 * (1.f / 128.f) + 1e-12f);
    float4 g4 = *(const float4*)(lng + lane * 4);
    float4 b4 = *(const float4*)(lnb + lane * 4);
    float o0 = g4.x * (hn[0] - mean) * inv + b4.x;
    float o1 = g4.y * (hn[1] - mean) * inv + b4.y;
    float o2 = g4.z * (hn[2] - mean) * inv + b4.z;
    float o3 = g4.w * (hn[3] - mean) * inv + b4.w;
    *(float4*)(xout + (size_t)w * 128 + lane * 4) = make_float4(o0, o1, o2, o3);
    st4h(g_xh + (size_t)w * 128 + lane * 4, o0, o1, o2, o3);
    st4h(g_kx + (size_t)w * 256 + 128 + lane * 4, o0, o1, o2, o3);
}

// ---------------- host ----------------
static void* sym_addr(const void* symbol) {
    void* p = nullptr;
    cudaGetSymbolAddress(&p, symbol);
    return p;
}

extern "C" void kernel_launch(void* const* d_in, const int* in_sizes, int n_in,
                              void* d_out, int out_size) {
    (void)in_sizes; (void)n_in; (void)out_size;
    const float* x     = (const float*)d_in[0];
    const int*   ei    = (const int*)d_in[1];
    const float* eattr = (const float*)d_in[2];
    const float* wq  = (const float*)d_in[3];  const float* bq  = (const float*)d_in[4];
    const float* wk  = (const float*)d_in[5];  const float* bk  = (const float*)d_in[6];
    const float* wv  = (const float*)d_in[7];  const float* bv  = (const float*)d_in[8];
    const float* wao = (const float*)d_in[9];  const float* bao = (const float*)d_in[10];
    const float* ln1g = (const float*)d_in[11]; const float* ln1b = (const float*)d_in[12];
    const float* wint = (const float*)d_in[13]; const float* bint = (const float*)d_in[14];
    const float* wout = (const float*)d_in[15]; const float* bout = (const float*)d_in[16];
    const float* ln2g = (const float*)d_in[17]; const float* ln2b = (const float*)d_in[18];
    const float* wih = (const float*)d_in[19];  const float* whh = (const float*)d_in[20];
    const float* bih = (const float*)d_in[21];  const float* bhh = (const float*)d_in[22];
    const float* ln3g = (const float*)d_in[23]; const float* ln3b = (const float*)d_in[24];
    float* out = (float*)d_out;

    __half* pP5   = (__half*)sym_addr(g_P5);
    __half* pKx   = (__half*)sym_addr(g_kx);
    __half* pSxeh = (__half*)sym_addr(g_sxeh);
    __half* pXh   = (__half*)sym_addr(g_xh);
    __half* pAtth = (__half*)sym_addr(g_atth);
    __half* pInth = (__half*)sym_addr(g_inth);
    __half* pMhh  = (__half*)sym_addr(g_mhh);
    float* pPre  = (float*)sym_addr(g_pre);
    float* pAtt  = (float*)sym_addr(g_att);
    float* pGrz  = (float*)sym_addr(g_grz);
    float* pGn   = (float*)sym_addr(g_gn);
    float* pH    = (float*)sym_addr(g_h);
    float* pX    = (float*)sym_addr(g_x);
    float* pBproj = (float*)sym_addr(g_bproj);
    float* pBav   = (float*)sym_addr(g_bav);
    float* pWbv   = (float*)sym_addr(g_wbv);
    float* pBrz   = (float*)sym_addr(g_brz);
    float* pBn    = (float*)sym_addr(g_bn);
    uint32_t* pImg = (uint32_t*)sym_addr(g_img);

    const int* srcp = ei;
    const int* dstp = ei + EE;

    const int SMB = 13824 * 4;
    cudaFuncSetAttribute(gemm_h<1, 2>, cudaFuncAttributeMaxDynamicSharedMemorySize, SMB);
    cudaFuncSetAttribute(gemm_h<2, 0>, cudaFuncAttributeMaxDynamicSharedMemorySize, SMB);
    cudaFuncSetAttribute(gemm_h<3, 2>, cudaFuncAttributeMaxDynamicSharedMemorySize, SMB);
    cudaFuncSetAttribute(gemm_h<1, 0>, cudaFuncAttributeMaxDynamicSharedMemorySize, SMB);
    cudaFuncSetAttribute(scan_kernel, cudaFuncAttributeMaxDynamicSharedMemorySize, 40960 * 4);

    const int MT = (NN + 127) / 128;
    const int RG = (NN + 7) / 8;

    // prep; launch 4 = proj q/qe GEMM (ncu slot)
    build_all<<<(270784 + 255) / 256, 256>>>(wq, wk, wv, wao, bq, bk, bv, bao, wih, whh, bih, bhh);
    prep_w_all<<<(393216 + 255) / 256, 256>>>(wint, wout, wih, whh);
    split_conv<<<(NN * 64 + 255) / 256, 256>>>(x);
    gemm_h<1, 2><<<dim3(MT, 5), 256, SMB>>>(pXh, 128, 0,
        pImg + (size_t)(IMG_PROJ + 2) * 9216, pBproj + 128, nullptr, pP5, NN, 2, 640);
    gemm_h<1, 2><<<dim3(MT, 1), 256, SMB>>>(pXh, 128, 0,
        pImg + (size_t)IMG_PROJ * 9216, pBproj, nullptr, pKx, NN, 2, 256);
    hist_kernel<<<(EE + 255) / 256, 256>>>(dstp);
    scan_kernel<<<1, 1024, 40960 * 4>>>();
    scatter_kernel<<<(EE + 255) / 256, 256>>>(srcp, dstp);
    gather_e<<<(int)(((size_t)EE * 64 + 255) / 256), 256>>>(eattr);

    for (int t = 0; t < 3; t++) {
        const float* xcur = (t == 0) ? x : pX;
        const float* hcur = (t == 0) ? x : pH;
        if (t > 0) {
            gemm_h<1, 2><<<dim3(MT, 5), 256, SMB>>>(pXh, 128, 0,
                pImg + (size_t)(IMG_PROJ + 2) * 9216, pBproj + 128, nullptr, pP5, NN, 2, 640);
            gemm_h<1, 2><<<dim3(MT, 1), 256, SMB>>>(pXh, 128, 0,
                pImg + (size_t)IMG_PROJ * 9216, pBproj, nullptr, pKx, NN, 2, 256);
        }
        gat2_kernel<<<RG, 256>>>();
        gemm_h<2, 0><<<dim3(MT, 1), 256, SMB>>>(pSxeh, 512, 0,
            pImg + (size_t)IMG_WAV4 * 9216, pBav, xcur, pPre, NN, 8, 128);
        ln_kernel<<<RG, 256>>>(pPre, ln1g, ln1b, pWbv, pAtt, pAtth, 128, 0);
        gemm_h<3, 2><<<dim3(MT, 4), 256, SMB>>>(pAtth, 128, 0,
            pImg + (size_t)IMG_WINT * 9216, bint, nullptr, pInth, NN, 2, 512);
        gemm_h<2, 0><<<dim3(MT, 1), 256, SMB>>>(pInth, 512, 0,
            pImg + (size_t)IMG_WOUT * 9216, bout, pAtt, pPre, NN, 8, 128);
        ln_kernel<<<RG, 256>>>(pPre, ln2g, ln2b, nullptr, nullptr, pMhh, 256, 0);
        gemm_h<1, 0><<<dim3(MT, 2), 256, SMB>>>(pMhh, 256, 0,
            pImg + (size_t)IMG_GRZ * 9216, pBrz, nullptr, pGrz, NN, 4, 256);
        gemm_h<1, 0><<<dim3(MT, 2), 256, SMB>>>(pMhh, 256, 128,
            pImg + (size_t)IMG_GN * 9216, pBn, nullptr, pGn, NN, 2, 256);
        gru_ln_kernel<<<RG, 256>>>(hcur, ln3g, ln3b, (t == 2) ? out : pX);
    }
}